// round 1
// baseline (speedup 1.0000x reference)
#include <cuda_runtime.h>
#include <math.h>

#define N_NODES 50000
#define N_EDGES 800000
#define OBS_DIM 128
#define H_DIM   128
#define ENC_H   512
#define OUT_LD  384

// ---------------- scratch (static device allocations; no cudaMalloc) ----------
__device__ float g_h1[(size_t)N_NODES * ENC_H];   // MLP hidden
__device__ float g_q[(size_t)N_NODES * H_DIM];
__device__ float g_k[(size_t)N_NODES * H_DIM];
__device__ float g_v[(size_t)N_NODES * H_DIM];
__device__ int   g_deg[N_NODES];
__device__ int   g_off[N_NODES + 1];
__device__ int   g_pos[N_NODES];
__device__ int   g_eids[N_EDGES];

// ---------------- CSR build ----------------------------------------------------
__global__ void k_zero_deg() {
    int i = blockIdx.x * blockDim.x + threadIdx.x;
    if (i < N_NODES) g_deg[i] = 0;
}

__global__ void k_count(const int* __restrict__ dst) {
    int e = blockIdx.x * blockDim.x + threadIdx.x;
    if (e < N_EDGES) atomicAdd(&g_deg[dst[e]], 1);
}

// single-block exclusive scan of g_deg -> g_off (and g_pos copy)
__global__ void k_scan() {
    __shared__ int sh[1024];
    __shared__ int s_carry;
    if (threadIdx.x == 0) s_carry = 0;
    __syncthreads();
    for (int base = 0; base < N_NODES; base += 1024) {
        int i = base + threadIdx.x;
        int v = (i < N_NODES) ? g_deg[i] : 0;
        sh[threadIdx.x] = v;
        __syncthreads();
        #pragma unroll
        for (int d = 1; d < 1024; d <<= 1) {
            int t = (threadIdx.x >= d) ? sh[threadIdx.x - d] : 0;
            __syncthreads();
            sh[threadIdx.x] += t;
            __syncthreads();
        }
        int carry = s_carry;
        if (i < N_NODES) {
            int excl = carry + sh[threadIdx.x] - v;
            g_off[i] = excl;
            g_pos[i] = excl;
        }
        __syncthreads();
        if (threadIdx.x == 0) s_carry = carry + sh[1023];
        __syncthreads();
    }
    if (threadIdx.x == 0) g_off[N_NODES] = s_carry;
}

__global__ void k_scatter(const int* __restrict__ dst) {
    int e = blockIdx.x * blockDim.x + threadIdx.x;
    if (e < N_EDGES) {
        int d = dst[e];
        int idx = atomicAdd(&g_pos[d], 1);
        g_eids[idx] = e;
    }
}

// ---------------- SGEMM: C[M,N] = A[M,K] (lda) @ B[K,N] (ldb) + bias ----------
// 128x128 block tile, BK=8, 256 threads, 8x8 microtile per thread.
template <bool RELU>
__global__ __launch_bounds__(256, 2)
void sgemm_kernel(const float* __restrict__ A, int lda,
                  const float* __restrict__ B, int ldb,
                  const float* __restrict__ bias,
                  float* __restrict__ C, int ldc,
                  int M, int K)
{
    __shared__ float As[8][128];   // [k][m] transposed
    __shared__ float Bs[8][128];   // [k][n]

    const int tid = threadIdx.x;
    const int tx = tid & 15;   // col group (8 cols each)
    const int ty = tid >> 4;   // row group (8 rows each)
    const int rowBase = blockIdx.x * 128;
    const int colBase = blockIdx.y * 128;

    const int aRow = tid >> 1;        // 0..127
    const int aCol = (tid & 1) * 4;   // 0 / 4
    const int bRow = tid >> 5;        // 0..7
    const int bCol = (tid & 31) * 4;  // 0..124

    float acc[8][8];
    #pragma unroll
    for (int i = 0; i < 8; i++)
        #pragma unroll
        for (int j = 0; j < 8; j++) acc[i][j] = 0.f;

    const int gr = rowBase + aRow;
    const bool aValid = (gr < M);

    for (int k0 = 0; k0 < K; k0 += 8) {
        float4 a4 = make_float4(0.f, 0.f, 0.f, 0.f);
        if (aValid)
            a4 = *reinterpret_cast<const float4*>(A + (size_t)gr * lda + k0 + aCol);
        As[aCol + 0][aRow] = a4.x;
        As[aCol + 1][aRow] = a4.y;
        As[aCol + 2][aRow] = a4.z;
        As[aCol + 3][aRow] = a4.w;

        float4 b4 = *reinterpret_cast<const float4*>(B + (size_t)(k0 + bRow) * ldb + colBase + bCol);
        *reinterpret_cast<float4*>(&Bs[bRow][bCol]) = b4;
        __syncthreads();

        #pragma unroll
        for (int kk = 0; kk < 8; kk++) {
            float a[8], b[8];
            float4 a0 = *reinterpret_cast<const float4*>(&As[kk][ty * 8]);
            float4 a1 = *reinterpret_cast<const float4*>(&As[kk][ty * 8 + 4]);
            float4 b0 = *reinterpret_cast<const float4*>(&Bs[kk][tx * 8]);
            float4 b1 = *reinterpret_cast<const float4*>(&Bs[kk][tx * 8 + 4]);
            a[0]=a0.x; a[1]=a0.y; a[2]=a0.z; a[3]=a0.w;
            a[4]=a1.x; a[5]=a1.y; a[6]=a1.z; a[7]=a1.w;
            b[0]=b0.x; b[1]=b0.y; b[2]=b0.z; b[3]=b0.w;
            b[4]=b1.x; b[5]=b1.y; b[6]=b1.z; b[7]=b1.w;
            #pragma unroll
            for (int i = 0; i < 8; i++)
                #pragma unroll
                for (int j = 0; j < 8; j++)
                    acc[i][j] += a[i] * b[j];
        }
        __syncthreads();
    }

    #pragma unroll
    for (int i = 0; i < 8; i++) {
        int r = rowBase + ty * 8 + i;
        if (r < M) {
            #pragma unroll
            for (int j = 0; j < 8; j++) {
                int c = colBase + tx * 8 + j;
                float val = acc[i][j] + bias[c];
                if (RELU) val = fmaxf(val, 0.f);
                C[(size_t)r * ldc + c] = val;
            }
        }
    }
}

// ---------------- GAT aggregation: one warp per destination node ---------------
// lane l holds dims [4l,4l+4); head = l>>2 (8 heads x 16 dims). Online softmax.
__global__ void k_gat(const float* __restrict__ q, const float* __restrict__ k,
                      const float* __restrict__ v, const int* __restrict__ srcArr,
                      float* __restrict__ zout, int ldz)
{
    int node = (blockIdx.x * blockDim.x + threadIdx.x) >> 5;
    int lane = threadIdx.x & 31;
    if (node >= N_NODES) return;

    const float4 qv = *reinterpret_cast<const float4*>(q + (size_t)node * H_DIM + lane * 4);

    float m = -1e30f, sum = 0.f;
    float ax = 0.f, ay = 0.f, az = 0.f, aw = 0.f;

    int beg = g_off[node], end = g_off[node + 1];
    for (int t = beg; t < end; t++) {
        int s = srcArr[g_eids[t]];
        const float4 kv = *reinterpret_cast<const float4*>(k + (size_t)s * H_DIM + lane * 4);
        float p = qv.x * kv.x + qv.y * kv.y + qv.z * kv.z + qv.w * kv.w;
        p += __shfl_xor_sync(0xffffffffu, p, 1);
        p += __shfl_xor_sync(0xffffffffu, p, 2);
        float score = p * 0.25f;   // 1/sqrt(HEAD_D=16)

        const float4 vv = *reinterpret_cast<const float4*>(v + (size_t)s * H_DIM + lane * 4);

        float mnew = fmaxf(m, score);
        float corr = __expf(m - mnew);
        float w = __expf(score - mnew);
        sum = sum * corr + w;
        ax = ax * corr + w * vv.x;
        ay = ay * corr + w * vv.y;
        az = az * corr + w * vv.z;
        aw = aw * corr + w * vv.w;
        m = mnew;
    }

    float inv = 1.f / (sum + 1e-9f);
    float4 o;
    o.x = fmaxf(ax * inv, 0.f);
    o.y = fmaxf(ay * inv, 0.f);
    o.z = fmaxf(az * inv, 0.f);
    o.w = fmaxf(aw * inv, 0.f);
    *reinterpret_cast<float4*>(zout + (size_t)node * ldz + lane * 4) = o;
}

// ---------------- host ---------------------------------------------------------
extern "C" void kernel_launch(void* const* d_in, const int* in_sizes, int n_in,
                              void* d_out, int out_size)
{
    const float* obs = (const float*)d_in[0];
    const int*   src = (const int*)d_in[1];
    const int*   dst = (const int*)d_in[2];
    const float* W1  = (const float*)d_in[3];  const float* b1  = (const float*)d_in[4];
    const float* W2  = (const float*)d_in[5];  const float* b2  = (const float*)d_in[6];
    const float* Wq1 = (const float*)d_in[7];  const float* bq1 = (const float*)d_in[8];
    const float* Wk1 = (const float*)d_in[9];  const float* bk1 = (const float*)d_in[10];
    const float* Wv1 = (const float*)d_in[11]; const float* bv1 = (const float*)d_in[12];
    const float* Wq2 = (const float*)d_in[13]; const float* bq2 = (const float*)d_in[14];
    const float* Wk2 = (const float*)d_in[15]; const float* bk2 = (const float*)d_in[16];
    const float* Wv2 = (const float*)d_in[17]; const float* bv2 = (const float*)d_in[18];
    float* out = (float*)d_out;

    float *p_h1, *p_q, *p_k, *p_v;
    cudaGetSymbolAddress((void**)&p_h1, g_h1);
    cudaGetSymbolAddress((void**)&p_q,  g_q);
    cudaGetSymbolAddress((void**)&p_k,  g_k);
    cudaGetSymbolAddress((void**)&p_v,  g_v);

    const int MT = (N_NODES + 127) / 128;   // 391 M-tiles

    // CSR build (independent of GEMMs)
    k_zero_deg<<<(N_NODES + 255) / 256, 256>>>();
    k_count<<<(N_EDGES + 255) / 256, 256>>>(dst);
    k_scan<<<1, 1024>>>();
    k_scatter<<<(N_EDGES + 255) / 256, 256>>>(dst);

    // MLP encoder: z1 -> out[:, 0:128]
    sgemm_kernel<true><<<dim3(MT, ENC_H / 128), 256>>>(obs, OBS_DIM, W1, ENC_H, b1,
                                                       p_h1, ENC_H, N_NODES, OBS_DIM);
    sgemm_kernel<true><<<dim3(MT, 1), 256>>>(p_h1, ENC_H, W2, H_DIM, b2,
                                             out + 0, OUT_LD, N_NODES, ENC_H);

    // GAT layer 1: x = out[:,0:128] -> z2 = out[:,128:256]
    sgemm_kernel<false><<<dim3(MT, 1), 256>>>(out + 0, OUT_LD, Wq1, H_DIM, bq1, p_q, H_DIM, N_NODES, H_DIM);
    sgemm_kernel<false><<<dim3(MT, 1), 256>>>(out + 0, OUT_LD, Wk1, H_DIM, bk1, p_k, H_DIM, N_NODES, H_DIM);
    sgemm_kernel<false><<<dim3(MT, 1), 256>>>(out + 0, OUT_LD, Wv1, H_DIM, bv1, p_v, H_DIM, N_NODES, H_DIM);
    k_gat<<<(N_NODES * 32 + 255) / 256, 256>>>(p_q, p_k, p_v, src, out + H_DIM, OUT_LD);

    // GAT layer 2: x = out[:,128:256] -> z3 = out[:,256:384]
    sgemm_kernel<false><<<dim3(MT, 1), 256>>>(out + H_DIM, OUT_LD, Wq2, H_DIM, bq2, p_q, H_DIM, N_NODES, H_DIM);
    sgemm_kernel<false><<<dim3(MT, 1), 256>>>(out + H_DIM, OUT_LD, Wk2, H_DIM, bk2, p_k, H_DIM, N_NODES, H_DIM);
    sgemm_kernel<false><<<dim3(MT, 1), 256>>>(out + H_DIM, OUT_LD, Wv2, H_DIM, bv2, p_v, H_DIM, N_NODES, H_DIM);
    k_gat<<<(N_NODES * 32 + 255) / 256, 256>>>(p_q, p_k, p_v, src, out + 2 * H_DIM, OUT_LD);
}

// round 2
// speedup vs baseline: 2.5501x; 2.5501x over previous
#include <cuda_runtime.h>
#include <math.h>

#define N_NODES 50000
#define N_EDGES 800000
#define OBS_DIM 128
#define H_DIM   128
#define ENC_H   512
#define OUT_LD  384
#define QKV_LD  384

// ---------------- scratch (static device allocations; no cudaMalloc) ----------
__device__ float g_h1[(size_t)N_NODES * ENC_H];     // MLP hidden
__device__ float g_qkv[(size_t)N_NODES * QKV_LD];   // packed q|k|v per node
__device__ float g_Wp[128 * 384];                   // packed Wq|Wk|Wv
__device__ float g_bp[384];
__device__ int   g_deg[N_NODES];
__device__ int   g_off[N_NODES + 1];
__device__ int   g_pos[N_NODES];
__device__ int   g_srcs[N_EDGES];                   // src node id in CSR-by-dst order

// ---------------- CSR build ----------------------------------------------------
__global__ void k_zero_deg() {
    int i = blockIdx.x * blockDim.x + threadIdx.x;
    if (i < N_NODES) g_deg[i] = 0;
}

__global__ void k_count(const int* __restrict__ dst) {
    int e = blockIdx.x * blockDim.x + threadIdx.x;
    if (e < N_EDGES) atomicAdd(&g_deg[dst[e]], 1);
}

__global__ void k_scan() {
    __shared__ int sh[1024];
    __shared__ int s_carry;
    if (threadIdx.x == 0) s_carry = 0;
    __syncthreads();
    for (int base = 0; base < N_NODES; base += 1024) {
        int i = base + threadIdx.x;
        int v = (i < N_NODES) ? g_deg[i] : 0;
        sh[threadIdx.x] = v;
        __syncthreads();
        #pragma unroll
        for (int d = 1; d < 1024; d <<= 1) {
            int t = (threadIdx.x >= d) ? sh[threadIdx.x - d] : 0;
            __syncthreads();
            sh[threadIdx.x] += t;
            __syncthreads();
        }
        int carry = s_carry;
        if (i < N_NODES) {
            int excl = carry + sh[threadIdx.x] - v;
            g_off[i] = excl;
            g_pos[i] = excl;
        }
        __syncthreads();
        if (threadIdx.x == 0) s_carry = carry + sh[1023];
        __syncthreads();
    }
    if (threadIdx.x == 0) g_off[N_NODES] = s_carry;
}

__global__ void k_scatter(const int* __restrict__ src, const int* __restrict__ dst) {
    int e = blockIdx.x * blockDim.x + threadIdx.x;
    if (e < N_EDGES) {
        int d = dst[e];
        int idx = atomicAdd(&g_pos[d], 1);
        g_srcs[idx] = src[e];
    }
}

// ---------------- TF32 tensor-core GEMM ----------------------------------------
// C[M,N] = A[M,K](lda) @ B[K,N](ldb) + bias, optional ReLU.
// CTA tile 128x128, BK=32, 8 warps (64x32 warp tile), mma.m16n8k8 tf32.
__device__ __forceinline__ unsigned f2tf32(float x) {
    unsigned r;
    asm volatile("cvt.rna.tf32.f32 %0, %1;" : "=r"(r) : "f"(x));
    return r;
}

__device__ __forceinline__ void mma_tf32(float* c, const unsigned* a, const unsigned* b) {
    asm volatile(
        "mma.sync.aligned.m16n8k8.row.col.f32.tf32.tf32.f32 "
        "{%0,%1,%2,%3}, {%4,%5,%6,%7}, {%8,%9}, {%0,%1,%2,%3};\n"
        : "+f"(c[0]), "+f"(c[1]), "+f"(c[2]), "+f"(c[3])
        : "r"(a[0]), "r"(a[1]), "r"(a[2]), "r"(a[3]), "r"(b[0]), "r"(b[1]));
}

#define AS_STRIDE 36    // 32 + 4 pad  (conflict-free fragment LDS)
#define BS_STRIDE 136   // 128 + 8 pad

template <bool RELU>
__global__ __launch_bounds__(256)
void gemm_tf32(const float* __restrict__ A, int lda,
               const float* __restrict__ B, int ldb,
               const float* __restrict__ bias,
               float* __restrict__ C, int ldc,
               int M, int K)
{
    __shared__ unsigned As[128 * AS_STRIDE];   // [m][k]
    __shared__ unsigned Bs[32 * BS_STRIDE];    // [k][n]

    const int tid  = threadIdx.x;
    const int lane = tid & 31;
    const int w    = tid >> 5;
    const int gid  = lane >> 2;
    const int tig  = lane & 3;
    const int warpM = w >> 2;     // 0..1 -> 64 rows each
    const int warpN = w & 3;      // 0..3 -> 32 cols each
    const int rowBase = blockIdx.x * 128;
    const int colBase = blockIdx.y * 128;

    // A loader: 128x32 tile, thread loads 4 float4
    const int a_r = tid >> 3;          // 0..31
    const int a_c = (tid & 7) * 4;     // 0..28
    // B loader: 32x128 tile, thread loads 4 float4
    const int b_k = tid >> 5;          // 0..7
    const int b_c = (tid & 31) * 4;    // 0..124

    float4 ra[4], rb[4];
    #pragma unroll
    for (int i = 0; i < 4; i++) {
        int r = rowBase + a_r + 32 * i;
        ra[i] = (r < M) ? *reinterpret_cast<const float4*>(A + (size_t)r * lda + a_c)
                        : make_float4(0.f, 0.f, 0.f, 0.f);
        rb[i] = *reinterpret_cast<const float4*>(B + (size_t)(b_k + 8 * i) * ldb + colBase + b_c);
    }

    float acc[4][4][4];
    #pragma unroll
    for (int mt = 0; mt < 4; mt++)
        #pragma unroll
        for (int nt = 0; nt < 4; nt++)
            #pragma unroll
            for (int j = 0; j < 4; j++) acc[mt][nt][j] = 0.f;

    int k0 = 0;
    for (;;) {
        #pragma unroll
        for (int i = 0; i < 4; i++) {
            uint4 ua = make_uint4(f2tf32(ra[i].x), f2tf32(ra[i].y), f2tf32(ra[i].z), f2tf32(ra[i].w));
            *reinterpret_cast<uint4*>(&As[(a_r + 32 * i) * AS_STRIDE + a_c]) = ua;
            uint4 ub = make_uint4(f2tf32(rb[i].x), f2tf32(rb[i].y), f2tf32(rb[i].z), f2tf32(rb[i].w));
            *reinterpret_cast<uint4*>(&Bs[(b_k + 8 * i) * BS_STRIDE + b_c]) = ub;
        }
        __syncthreads();

        k0 += 32;
        const bool more = (k0 < K);
        if (more) {
            #pragma unroll
            for (int i = 0; i < 4; i++) {
                int r = rowBase + a_r + 32 * i;
                ra[i] = (r < M) ? *reinterpret_cast<const float4*>(A + (size_t)r * lda + k0 + a_c)
                                : make_float4(0.f, 0.f, 0.f, 0.f);
                rb[i] = *reinterpret_cast<const float4*>(B + (size_t)(k0 + b_k + 8 * i) * ldb + colBase + b_c);
            }
        }

        #pragma unroll
        for (int kk = 0; kk < 4; kk++) {
            unsigned af[4][4], bf[4][2];
            #pragma unroll
            for (int mt = 0; mt < 4; mt++) {
                int m0 = warpM * 64 + mt * 16 + gid;
                const unsigned* p = &As[m0 * AS_STRIDE + kk * 8 + tig];
                af[mt][0] = p[0];
                af[mt][1] = p[8 * AS_STRIDE];
                af[mt][2] = p[4];
                af[mt][3] = p[8 * AS_STRIDE + 4];
            }
            #pragma unroll
            for (int nt = 0; nt < 4; nt++) {
                int n0 = warpN * 32 + nt * 8 + gid;
                const unsigned* p = &Bs[(kk * 8 + tig) * BS_STRIDE + n0];
                bf[nt][0] = p[0];
                bf[nt][1] = p[4 * BS_STRIDE];
            }
            #pragma unroll
            for (int mt = 0; mt < 4; mt++)
                #pragma unroll
                for (int nt = 0; nt < 4; nt++)
                    mma_tf32(acc[mt][nt], af[mt], bf[nt]);
        }
        __syncthreads();
        if (!more) break;
    }

    // epilogue: c0,c1 at (row, 2t/2t+1); c2,c3 at (row+8, same cols)
    #pragma unroll
    for (int mt = 0; mt < 4; mt++) {
        int r0 = rowBase + warpM * 64 + mt * 16 + gid;
        #pragma unroll
        for (int nt = 0; nt < 4; nt++) {
            int c = colBase + warpN * 32 + nt * 8 + tig * 2;
            float2 bi = *reinterpret_cast<const float2*>(bias + c);
            if (r0 < M) {
                float2 o;
                o.x = acc[mt][nt][0] + bi.x;
                o.y = acc[mt][nt][1] + bi.y;
                if (RELU) { o.x = fmaxf(o.x, 0.f); o.y = fmaxf(o.y, 0.f); }
                *reinterpret_cast<float2*>(C + (size_t)r0 * ldc + c) = o;
            }
            if (r0 + 8 < M) {
                float2 o;
                o.x = acc[mt][nt][2] + bi.x;
                o.y = acc[mt][nt][3] + bi.y;
                if (RELU) { o.x = fmaxf(o.x, 0.f); o.y = fmaxf(o.y, 0.f); }
                *reinterpret_cast<float2*>(C + (size_t)(r0 + 8) * ldc + c) = o;
            }
        }
    }
}

// ---------------- QKV weight pack ----------------------------------------------
__global__ void k_pack_qkv(const float* __restrict__ Wq, const float* __restrict__ bq,
                           const float* __restrict__ Wk, const float* __restrict__ bk,
                           const float* __restrict__ Wv, const float* __restrict__ bv)
{
    int i = blockIdx.x * blockDim.x + threadIdx.x;
    if (i < 128 * 128) {
        int k = i >> 7, j = i & 127;
        g_Wp[k * 384 + j]       = Wq[i];
        g_Wp[k * 384 + 128 + j] = Wk[i];
        g_Wp[k * 384 + 256 + j] = Wv[i];
        if (i < 128) { g_bp[i] = bq[i]; g_bp[128 + i] = bk[i]; g_bp[256 + i] = bv[i]; }
    }
}

// ---------------- GAT aggregation: one warp per destination node ---------------
// q/k/v packed: qkv[node][0:128)=q, [128:256)=k, [256:384)=v. Online softmax.
__global__ void k_gat(const float* __restrict__ qkv, float* __restrict__ zout, int ldz)
{
    int node = (blockIdx.x * blockDim.x + threadIdx.x) >> 5;
    int lane = threadIdx.x & 31;
    if (node >= N_NODES) return;

    const float4 qv = *reinterpret_cast<const float4*>(qkv + (size_t)node * QKV_LD + lane * 4);

    float m = -1e30f, sum = 0.f;
    float ax = 0.f, ay = 0.f, az = 0.f, aw = 0.f;

    int beg = g_off[node], end = g_off[node + 1];
    for (int t = beg; t < end; t++) {
        int s = g_srcs[t];
        const float* base = qkv + (size_t)s * QKV_LD;
        const float4 kv = *reinterpret_cast<const float4*>(base + 128 + lane * 4);
        float p = qv.x * kv.x + qv.y * kv.y + qv.z * kv.z + qv.w * kv.w;
        p += __shfl_xor_sync(0xffffffffu, p, 1);
        p += __shfl_xor_sync(0xffffffffu, p, 2);
        float score = p * 0.25f;   // 1/sqrt(16)

        const float4 vv = *reinterpret_cast<const float4*>(base + 256 + lane * 4);

        float mnew = fmaxf(m, score);
        float corr = __expf(m - mnew);
        float wgt  = __expf(score - mnew);
        sum = sum * corr + wgt;
        ax = ax * corr + wgt * vv.x;
        ay = ay * corr + wgt * vv.y;
        az = az * corr + wgt * vv.z;
        aw = aw * corr + wgt * vv.w;
        m = mnew;
    }

    float inv = 1.f / (sum + 1e-9f);
    float4 o;
    o.x = fmaxf(ax * inv, 0.f);
    o.y = fmaxf(ay * inv, 0.f);
    o.z = fmaxf(az * inv, 0.f);
    o.w = fmaxf(aw * inv, 0.f);
    *reinterpret_cast<float4*>(zout + (size_t)node * ldz + lane * 4) = o;
}

// ---------------- host ---------------------------------------------------------
extern "C" void kernel_launch(void* const* d_in, const int* in_sizes, int n_in,
                              void* d_out, int out_size)
{
    const float* obs = (const float*)d_in[0];
    const int*   src = (const int*)d_in[1];
    const int*   dst = (const int*)d_in[2];
    const float* W1  = (const float*)d_in[3];  const float* b1  = (const float*)d_in[4];
    const float* W2  = (const float*)d_in[5];  const float* b2  = (const float*)d_in[6];
    const float* Wq1 = (const float*)d_in[7];  const float* bq1 = (const float*)d_in[8];
    const float* Wk1 = (const float*)d_in[9];  const float* bk1 = (const float*)d_in[10];
    const float* Wv1 = (const float*)d_in[11]; const float* bv1 = (const float*)d_in[12];
    const float* Wq2 = (const float*)d_in[13]; const float* bq2 = (const float*)d_in[14];
    const float* Wk2 = (const float*)d_in[15]; const float* bk2 = (const float*)d_in[16];
    const float* Wv2 = (const float*)d_in[17]; const float* bv2 = (const float*)d_in[18];
    float* out = (float*)d_out;

    float *p_h1, *p_qkv, *p_Wp, *p_bp;
    cudaGetSymbolAddress((void**)&p_h1,  g_h1);
    cudaGetSymbolAddress((void**)&p_qkv, g_qkv);
    cudaGetSymbolAddress((void**)&p_Wp,  g_Wp);
    cudaGetSymbolAddress((void**)&p_bp,  g_bp);

    const int MT = (N_NODES + 127) / 128;   // 391

    // CSR build
    k_zero_deg<<<(N_NODES + 255) / 256, 256>>>();
    k_count<<<(N_EDGES + 255) / 256, 256>>>(dst);
    k_scan<<<1, 1024>>>();
    k_scatter<<<(N_EDGES + 255) / 256, 256>>>(src, dst);

    // MLP encoder: z1 -> out[:, 0:128]
    gemm_tf32<true><<<dim3(MT, ENC_H / 128), 256>>>(obs, OBS_DIM, W1, ENC_H, b1,
                                                    p_h1, ENC_H, N_NODES, OBS_DIM);
    gemm_tf32<true><<<dim3(MT, 1), 256>>>(p_h1, ENC_H, W2, H_DIM, b2,
                                          out + 0, OUT_LD, N_NODES, ENC_H);

    // GAT layer 1
    k_pack_qkv<<<(128 * 128 + 255) / 256, 256>>>(Wq1, bq1, Wk1, bk1, Wv1, bv1);
    gemm_tf32<false><<<dim3(MT, 3), 256>>>(out + 0, OUT_LD, p_Wp, 384, p_bp,
                                           p_qkv, QKV_LD, N_NODES, H_DIM);
    k_gat<<<(N_NODES * 32 + 255) / 256, 256>>>(p_qkv, out + H_DIM, OUT_LD);

    // GAT layer 2
    k_pack_qkv<<<(128 * 128 + 255) / 256, 256>>>(Wq2, bq2, Wk2, bk2, Wv2, bv2);
    gemm_tf32<false><<<dim3(MT, 3), 256>>>(out + H_DIM, OUT_LD, p_Wp, 384, p_bp,
                                           p_qkv, QKV_LD, N_NODES, H_DIM);
    k_gat<<<(N_NODES * 32 + 255) / 256, 256>>>(p_qkv, out + 2 * H_DIM, OUT_LD);
}

// round 4
// speedup vs baseline: 2.8789x; 1.1289x over previous
#include <cuda_runtime.h>
#include <cstdint>
#include <math.h>

#define N_NODES 50000
#define N_EDGES 800000
#define OBS_DIM 128
#define H_DIM   128
#define ENC_H   512
#define OUT_LD  384
#define QKV_LD  384
#define NB_SCAN 196   // ceil(50000/256)

// ---------------- scratch ------------------------------------------------------
__device__ uint32_t g_obsT[(size_t)N_NODES * OBS_DIM];  // tf32 obs
__device__ uint32_t g_h1[(size_t)N_NODES * ENC_H];      // tf32 MLP hidden
__device__ uint32_t g_xt[(size_t)N_NODES * H_DIM];      // tf32 current x (GEMM A)
__device__ float    g_qkv[(size_t)N_NODES * QKV_LD];    // fp32 packed q|k|v
__device__ uint32_t g_W1t[512 * 128];                   // tf32 [N,K] weights
__device__ uint32_t g_W2t[128 * 512];
__device__ uint32_t g_Wt1[384 * 128];
__device__ uint32_t g_Wt2[384 * 128];
__device__ float    g_bp1[384];
__device__ float    g_bp2[384];
__device__ int      g_deg[N_NODES];
__device__ int      g_off[N_NODES + 1];
__device__ int      g_pos[N_NODES];
__device__ int      g_srcs[N_EDGES];
__device__ int      g_bsum[256];

// ---------------- helpers ------------------------------------------------------
__device__ __forceinline__ uint32_t f2t(float x) {
    uint32_t r;
    asm volatile("cvt.rna.tf32.f32 %0, %1;" : "=r"(r) : "f"(x));
    return r;
}
__device__ __forceinline__ uint32_t smem_u32(const void* p) {
    uint32_t a;
    asm("{ .reg .u64 t; cvta.to.shared.u64 t, %1; cvt.u32.u64 %0, t; }" : "=r"(a) : "l"(p));
    return a;
}
__device__ __forceinline__ void cp16(uint32_t sm_addr, const void* g, int nbytes) {
    asm volatile("cp.async.cg.shared.global [%0], [%1], 16, %2;"
                 :: "r"(sm_addr), "l"(g), "r"(nbytes) : "memory");
}
__device__ __forceinline__ void cp_commit() {
    asm volatile("cp.async.commit_group;" ::: "memory");
}
template <int N>
__device__ __forceinline__ void cp_wait() {
    asm volatile("cp.async.wait_group %0;" :: "n"(N) : "memory");
}
__device__ __forceinline__ void mma_tf32(float* c, const uint32_t* a, const uint32_t* b) {
    asm volatile(
        "mma.sync.aligned.m16n8k8.row.col.f32.tf32.tf32.f32 "
        "{%0,%1,%2,%3}, {%4,%5,%6,%7}, {%8,%9}, {%0,%1,%2,%3};\n"
        : "+f"(c[0]), "+f"(c[1]), "+f"(c[2]), "+f"(c[3])
        : "r"(a[0]), "r"(a[1]), "r"(a[2]), "r"(a[3]), "r"(b[0]), "r"(b[1]));
}

// ---------------- pipelined TF32 GEMM -------------------------------------------
// C[M,N] = A[M,K] @ Bt^T  (+bias, opt ReLU); A,Bt are pre-converted tf32 (uint32).
// A: [M,K] row-major (lda). Bt: [Ntot,K] row-major. CTA tile 128x128, BK=32,
// 3-stage cp.async pipeline. smem layout per stage: A[128][36], B[128][36] (pad).
#define ST_FLOATS 36
#define ST_OP     (128 * ST_FLOATS)           // 4608 floats per operand
#define ST_BYTES  (2 * ST_OP * 4)             // 36864 B per stage
#define GEMM_SMEM (3 * ST_BYTES)              // 110592 B

__device__ __forceinline__ void load_stage(
    uint32_t sbase, int stage, const uint32_t* __restrict__ A, int lda,
    const uint32_t* __restrict__ Bt, int K, int rowBase, int colBase,
    int k0, int M, int tid)
{
    uint32_t st = sbase + stage * ST_BYTES;
    #pragma unroll
    for (int p = 0; p < 4; p++) {
        int idx = tid + (p << 8);
        int row = idx >> 3;
        int kc  = idx & 7;
        uint32_t off = row * 144 + kc * 16;
        int gr = rowBase + row;
        int okA = (gr < M) ? 16 : 0;
        const uint32_t* ga = A + (size_t)(okA ? gr : 0) * lda + k0 + kc * 4;
        cp16(st + off, ga, okA);
        const uint32_t* gb = Bt + (size_t)(colBase + row) * K + k0 + kc * 4;
        cp16(st + ST_OP * 4 + off, gb, 16);
    }
    cp_commit();
}

template <bool RELU, bool WF32, bool WT32>
__global__ __launch_bounds__(256, 2)
void gemm_tc(const uint32_t* __restrict__ A, int lda,
             const uint32_t* __restrict__ Bt,
             const float* __restrict__ bias,
             float* __restrict__ C, int ldc,
             uint32_t* __restrict__ Ct, int ldct,
             int M, int K)
{
    extern __shared__ char sm[];
    const uint32_t sbase = smem_u32(sm);
    const int tid  = threadIdx.x;
    const int lane = tid & 31;
    const int w    = tid >> 5;
    const int gid  = lane >> 2;
    const int tig  = lane & 3;
    const int warpM = w >> 2;     // 0..1
    const int warpN = w & 3;      // 0..3
    const int rowBase = blockIdx.x * 128;
    const int colBase = blockIdx.y * 128;
    const int nCh = K >> 5;

    float acc[4][4][4];
    #pragma unroll
    for (int mt = 0; mt < 4; mt++)
        #pragma unroll
        for (int nt = 0; nt < 4; nt++)
            #pragma unroll
            for (int j = 0; j < 4; j++) acc[mt][nt][j] = 0.f;

    load_stage(sbase, 0, A, lda, Bt, K, rowBase, colBase, 0, M, tid);
    load_stage(sbase, 1, A, lda, Bt, K, rowBase, colBase, 32, M, tid);

    int stage = 0;
    #pragma unroll 1
    for (int c = 0; c < nCh; c++) {
        if (c + 1 < nCh) cp_wait<1>(); else cp_wait<0>();
        __syncthreads();
        if (c + 2 < nCh) {
            int ns = stage + 2; if (ns >= 3) ns -= 3;
            load_stage(sbase, ns, A, lda, Bt, K, rowBase, colBase, (c + 2) << 5, M, tid);
        }
        const uint32_t* sA = reinterpret_cast<const uint32_t*>(sm + stage * ST_BYTES);
        const uint32_t* sB = sA + ST_OP;
        #pragma unroll
        for (int kk = 0; kk < 4; kk++) {
            uint32_t af[4][4], bf[4][2];
            #pragma unroll
            for (int mt = 0; mt < 4; mt++) {
                const uint32_t* p = &sA[(warpM * 64 + mt * 16 + gid) * ST_FLOATS + kk * 8 + tig];
                af[mt][0] = p[0];
                af[mt][1] = p[8 * ST_FLOATS];
                af[mt][2] = p[4];
                af[mt][3] = p[8 * ST_FLOATS + 4];
            }
            #pragma unroll
            for (int nt = 0; nt < 4; nt++) {
                const uint32_t* p = &sB[(warpN * 32 + nt * 8 + gid) * ST_FLOATS + kk * 8 + tig];
                bf[nt][0] = p[0];
                bf[nt][1] = p[4];
            }
            #pragma unroll
            for (int mt = 0; mt < 4; mt++)
                #pragma unroll
                for (int nt = 0; nt < 4; nt++)
                    mma_tf32(acc[mt][nt], af[mt], bf[nt]);
        }
        stage++; if (stage >= 3) stage = 0;
    }

    // epilogue
    #pragma unroll
    for (int mt = 0; mt < 4; mt++) {
        int r0 = rowBase + warpM * 64 + mt * 16 + gid;
        #pragma unroll
        for (int nt = 0; nt < 4; nt++) {
            int cc = colBase + warpN * 32 + nt * 8 + tig * 2;
            float2 bi = *reinterpret_cast<const float2*>(bias + cc);
            #pragma unroll
            for (int h = 0; h < 2; h++) {
                int r = r0 + h * 8;
                if (r < M) {
                    float ox = acc[mt][nt][h * 2 + 0] + bi.x;
                    float oy = acc[mt][nt][h * 2 + 1] + bi.y;
                    if (RELU) { ox = fmaxf(ox, 0.f); oy = fmaxf(oy, 0.f); }
                    if (WF32)
                        *reinterpret_cast<float2*>(C + (size_t)r * ldc + cc) = make_float2(ox, oy);
                    if (WT32) {
                        uint2 u = make_uint2(f2t(ox), f2t(oy));
                        *reinterpret_cast<uint2*>(Ct + (size_t)r * ldct + cc) = u;
                    }
                }
            }
        }
    }
}

// ---------------- conversions / weight packing ----------------------------------
__global__ void k_cvt(const float* __restrict__ X, uint32_t* __restrict__ Y, int n) {
    int i = blockIdx.x * blockDim.x + threadIdx.x;
    if (i < n) Y[i] = f2t(X[i]);
}

__global__ void k_packT(const float* __restrict__ W, uint32_t* __restrict__ Wt, int K, int N) {
    int i = blockIdx.x * blockDim.x + threadIdx.x;
    if (i < K * N) {
        int k = i / N, n = i % N;
        Wt[(size_t)n * K + k] = f2t(W[i]);
    }
}

__global__ void k_pack_qkvT(const float* __restrict__ Wq, const float* __restrict__ bq,
                            const float* __restrict__ Wk, const float* __restrict__ bk,
                            const float* __restrict__ Wv, const float* __restrict__ bv,
                            uint32_t* __restrict__ Wt, float* __restrict__ bp)
{
    int i = blockIdx.x * blockDim.x + threadIdx.x;
    if (i < 128 * 128) {
        int k = i >> 7, n = i & 127;
        Wt[(size_t)n * 128 + k]         = f2t(Wq[i]);
        Wt[(size_t)(n + 128) * 128 + k] = f2t(Wk[i]);
        Wt[(size_t)(n + 256) * 128 + k] = f2t(Wv[i]);
        if (i < 128) { bp[i] = bq[i]; bp[128 + i] = bk[i]; bp[256 + i] = bv[i]; }
    }
}

// ---------------- CSR build -----------------------------------------------------
__global__ void k_zero_deg() {
    int i = blockIdx.x * blockDim.x + threadIdx.x;
    if (i < N_NODES) g_deg[i] = 0;
}

__global__ void k_count(const int* __restrict__ dst) {
    int e = blockIdx.x * blockDim.x + threadIdx.x;
    if (e < N_EDGES) atomicAdd(&g_deg[dst[e]], 1);
}

__device__ __forceinline__ int block_excl_scan(int v, int tid) {
    int lane = tid & 31, w = tid >> 5;
    int x = v;
    #pragma unroll
    for (int d = 1; d < 32; d <<= 1) {
        int t = __shfl_up_sync(0xffffffffu, x, d);
        if (lane >= d) x += t;
    }
    __shared__ int ws[8];
    if (lane == 31) ws[w] = x;
    __syncthreads();
    if (w == 0) {
        int y = (lane < 8) ? ws[lane] : 0;
        #pragma unroll
        for (int d = 1; d < 8; d <<= 1) {
            int t = __shfl_up_sync(0xffffffffu, y, d);
            if (lane >= d) y += t;
        }
        if (lane < 8) ws[lane] = y;
    }
    __syncthreads();
    return x - v + ((w > 0) ? ws[w - 1] : 0);
}

__global__ void k_scan1() {
    int tid = threadIdx.x;
    int i = blockIdx.x * 256 + tid;
    int v = (i < N_NODES) ? g_deg[i] : 0;
    int excl = block_excl_scan(v, tid);
    if (i < N_NODES) g_off[i] = excl;
    if (tid == 255) g_bsum[blockIdx.x] = excl + v;
}

__global__ void k_scan2() {
    int tid = threadIdx.x;
    int v = (tid < NB_SCAN) ? g_bsum[tid] : 0;
    int excl = block_excl_scan(v, tid);
    if (tid < NB_SCAN) g_bsum[tid] = excl;
    if (tid == NB_SCAN - 1) g_off[N_NODES] = excl + v;
}

__global__ void k_scan3() {
    int i = blockIdx.x * 256 + threadIdx.x;
    if (i < N_NODES) {
        int o = g_off[i] + g_bsum[blockIdx.x];
        g_off[i] = o;
        g_pos[i] = o;
    }
}

__global__ void k_scatter(const int* __restrict__ src, const int* __restrict__ dst) {
    int e = blockIdx.x * blockDim.x + threadIdx.x;
    if (e < N_EDGES) {
        int d = dst[e];
        int idx = atomicAdd(&g_pos[d], 1);
        g_srcs[idx] = src[e];
    }
}

// ---------------- GAT: one warp per destination node ----------------------------
template <bool WT32>
__global__ void k_gat(const float* __restrict__ qkv, float* __restrict__ zout, int ldz,
                      uint32_t* __restrict__ xt)
{
    int node = (blockIdx.x * blockDim.x + threadIdx.x) >> 5;
    int lane = threadIdx.x & 31;
    if (node >= N_NODES) return;

    const float4 qv = *reinterpret_cast<const float4*>(qkv + (size_t)node * QKV_LD + lane * 4);

    float m = -1e30f, sum = 0.f;
    float ax = 0.f, ay = 0.f, az = 0.f, aw = 0.f;

    int t = g_off[node], end = g_off[node + 1];
    while (t < end) {
        int nload = min(32, end - t);
        int sj = (lane < nload) ? __ldg(&g_srcs[t + lane]) : 0;
        for (int j = 0; j < nload; j++) {
            int s = __shfl_sync(0xffffffffu, sj, j);
            const float* base = qkv + (size_t)s * QKV_LD;
            const float4 kv = *reinterpret_cast<const float4*>(base + 128 + lane * 4);
            float p = qv.x * kv.x + qv.y * kv.y + qv.z * kv.z + qv.w * kv.w;
            p += __shfl_xor_sync(0xffffffffu, p, 1);
            p += __shfl_xor_sync(0xffffffffu, p, 2);
            float score = p * 0.25f;   // 1/sqrt(16)

            const float4 vv = *reinterpret_cast<const float4*>(base + 256 + lane * 4);

            float mnew = fmaxf(m, score);
            float corr = __expf(m - mnew);
            float wgt  = __expf(score - mnew);
            sum = sum * corr + wgt;
            ax = ax * corr + wgt * vv.x;
            ay = ay * corr + wgt * vv.y;
            az = az * corr + wgt * vv.z;
            aw = aw * corr + wgt * vv.w;
            m = mnew;
        }
        t += nload;
    }

    float inv = 1.f / (sum + 1e-9f);
    float4 o;
    o.x = fmaxf(ax * inv, 0.f);
    o.y = fmaxf(ay * inv, 0.f);
    o.z = fmaxf(az * inv, 0.f);
    o.w = fmaxf(aw * inv, 0.f);
    *reinterpret_cast<float4*>(zout + (size_t)node * ldz + lane * 4) = o;
    if (WT32) {
        uint4 u = make_uint4(f2t(o.x), f2t(o.y), f2t(o.z), f2t(o.w));
        *reinterpret_cast<uint4*>(xt + (size_t)node * H_DIM + lane * 4) = u;
    }
}

// ---------------- host ----------------------------------------------------------
extern "C" void kernel_launch(void* const* d_in, const int* in_sizes, int n_in,
                              void* d_out, int out_size)
{
    const float* obs = (const float*)d_in[0];
    const int*   src = (const int*)d_in[1];
    const int*   dst = (const int*)d_in[2];
    const float* W1  = (const float*)d_in[3];  const float* b1  = (const float*)d_in[4];
    const float* W2  = (const float*)d_in[5];  const float* b2  = (const float*)d_in[6];
    const float* Wq1 = (const float*)d_in[7];  const float* bq1 = (const float*)d_in[8];
    const float* Wk1 = (const float*)d_in[9];  const float* bk1 = (const float*)d_in[10];
    const float* Wv1 = (const float*)d_in[11]; const float* bv1 = (const float*)d_in[12];
    const float* Wq2 = (const float*)d_in[13]; const float* bq2 = (const float*)d_in[14];
    const float* Wk2 = (const float*)d_in[15]; const float* bk2 = (const float*)d_in[16];
    const float* Wv2 = (const float*)d_in[17]; const float* bv2 = (const float*)d_in[18];
    float* out = (float*)d_out;

    uint32_t *p_obsT, *p_h1, *p_xt, *p_W1t, *p_W2t, *p_Wt1, *p_Wt2;
    float *p_qkv, *p_bp1, *p_bp2;
    cudaGetSymbolAddress((void**)&p_obsT, g_obsT);
    cudaGetSymbolAddress((void**)&p_h1,   g_h1);
    cudaGetSymbolAddress((void**)&p_xt,   g_xt);
    cudaGetSymbolAddress((void**)&p_qkv,  g_qkv);
    cudaGetSymbolAddress((void**)&p_W1t,  g_W1t);
    cudaGetSymbolAddress((void**)&p_W2t,  g_W2t);
    cudaGetSymbolAddress((void**)&p_Wt1,  g_Wt1);
    cudaGetSymbolAddress((void**)&p_Wt2,  g_Wt2);
    cudaGetSymbolAddress((void**)&p_bp1,  g_bp1);
    cudaGetSymbolAddress((void**)&p_bp2,  g_bp2);

    cudaFuncSetAttribute(gemm_tc<true, false, true>,  cudaFuncAttributeMaxDynamicSharedMemorySize, GEMM_SMEM);
    cudaFuncSetAttribute(gemm_tc<true, true, true>,   cudaFuncAttributeMaxDynamicSharedMemorySize, GEMM_SMEM);
    cudaFuncSetAttribute(gemm_tc<false, true, false>, cudaFuncAttributeMaxDynamicSharedMemorySize, GEMM_SMEM);

    const int MT = (N_NODES + 127) / 128;   // 391

    // conversions + weight packs (tiny)
    k_cvt<<<(N_NODES * OBS_DIM + 255) / 256, 256>>>(obs, p_obsT, N_NODES * OBS_DIM);
    k_packT<<<(128 * 512 + 255) / 256, 256>>>(W1, p_W1t, OBS_DIM, ENC_H);
    k_packT<<<(512 * 128 + 255) / 256, 256>>>(W2, p_W2t, ENC_H, H_DIM);
    k_pack_qkvT<<<(128 * 128 + 255) / 256, 256>>>(Wq1, bq1, Wk1, bk1, Wv1, bv1, p_Wt1, p_bp1);
    k_pack_qkvT<<<(128 * 128 + 255) / 256, 256>>>(Wq2, bq2, Wk2, bk2, Wv2, bv2, p_Wt2, p_bp2);

    // CSR build
    k_zero_deg<<<(N_NODES + 255) / 256, 256>>>();
    k_count<<<(N_EDGES + 255) / 256, 256>>>(dst);
    k_scan1<<<NB_SCAN, 256>>>();
    k_scan2<<<1, 256>>>();
    k_scan3<<<NB_SCAN, 256>>>();
    k_scatter<<<(N_EDGES + 255) / 256, 256>>>(src, dst);

    // MLP encoder
    gemm_tc<true, false, true><<<dim3(MT, ENC_H / 128), 256, GEMM_SMEM>>>(
        p_obsT, OBS_DIM, p_W1t, b1, nullptr, 0, p_h1, ENC_H, N_NODES, OBS_DIM);
    gemm_tc<true, true, true><<<dim3(MT, 1), 256, GEMM_SMEM>>>(
        p_h1, ENC_H, p_W2t, b2, out + 0, OUT_LD, p_xt, H_DIM, N_NODES, ENC_H);

    // GAT layer 1
    gemm_tc<false, true, false><<<dim3(MT, 3), 256, GEMM_SMEM>>>(
        p_xt, H_DIM, p_Wt1, p_bp1, p_qkv, QKV_LD, nullptr, 0, N_NODES, H_DIM);
    k_gat<true><<<(N_NODES * 32 + 255) / 256, 256>>>(p_qkv, out + H_DIM, OUT_LD, p_xt);

    // GAT layer 2
    gemm_tc<false, true, false><<<dim3(MT, 3), 256, GEMM_SMEM>>>(
        p_xt, H_DIM, p_Wt2, p_bp2, p_qkv, QKV_LD, nullptr, 0, N_NODES, H_DIM);
    k_gat<false><<<(N_NODES * 32 + 255) / 256, 256>>>(p_qkv, out + 2 * H_DIM, OUT_LD, nullptr);
}

// round 6
// speedup vs baseline: 2.9396x; 1.0211x over previous
#include <cuda_runtime.h>
#include <cstdint>
#include <math.h>

#define N_NODES 50000
#define N_EDGES 800000
#define OBS_DIM 128
#define H_DIM   128
#define ENC_H   512
#define OUT_LD  384
#define QKV_LD  384
#define NB_SCAN 196   // ceil(50000/256)

// ---------------- scratch ------------------------------------------------------
__device__ uint32_t g_obsT[(size_t)N_NODES * OBS_DIM];  // tf32 obs
__device__ uint32_t g_h1[(size_t)N_NODES * ENC_H];      // tf32 MLP hidden
__device__ uint32_t g_xt[(size_t)N_NODES * H_DIM];      // tf32 current x (GEMM A)
__device__ float    g_qkv[(size_t)N_NODES * QKV_LD];    // fp32 packed q|k|v
__device__ uint32_t g_W1t[512 * 128];                   // tf32 [N,K] weights
__device__ uint32_t g_W2t[128 * 512];
__device__ uint32_t g_Wt1[384 * 128];
__device__ uint32_t g_Wt2[384 * 128];
__device__ float    g_bp1[384];
__device__ float    g_bp2[384];
__device__ int      g_deg[N_NODES];
__device__ int      g_off[N_NODES + 1];
__device__ int      g_pos[N_NODES];
__device__ int      g_srcs[N_EDGES];
__device__ int      g_bsum[256];

// ---------------- helpers ------------------------------------------------------
__device__ __forceinline__ uint32_t f2t(float x) {
    uint32_t r;
    asm volatile("cvt.rna.tf32.f32 %0, %1;" : "=r"(r) : "f"(x));
    return r;
}
__device__ __forceinline__ uint32_t smem_u32(const void* p) {
    uint32_t a;
    asm("{ .reg .u64 t; cvta.to.shared.u64 t, %1; cvt.u32.u64 %0, t; }" : "=r"(a) : "l"(p));
    return a;
}
__device__ __forceinline__ void cp16(uint32_t sm_addr, const void* g, int nbytes) {
    asm volatile("cp.async.cg.shared.global [%0], [%1], 16, %2;"
                 :: "r"(sm_addr), "l"(g), "r"(nbytes) : "memory");
}
__device__ __forceinline__ void cp_commit() {
    asm volatile("cp.async.commit_group;" ::: "memory");
}
template <int N>
__device__ __forceinline__ void cp_wait() {
    asm volatile("cp.async.wait_group %0;" :: "n"(N) : "memory");
}
__device__ __forceinline__ void mma_tf32(float* c, const uint32_t* a, const uint32_t* b) {
    asm volatile(
        "mma.sync.aligned.m16n8k8.row.col.f32.tf32.tf32.f32 "
        "{%0,%1,%2,%3}, {%4,%5,%6,%7}, {%8,%9}, {%0,%1,%2,%3};\n"
        : "+f"(c[0]), "+f"(c[1]), "+f"(c[2]), "+f"(c[3])
        : "r"(a[0]), "r"(a[1]), "r"(a[2]), "r"(a[3]), "r"(b[0]), "r"(b[1]));
}

// ---------------- pipelined TF32 GEMM -------------------------------------------
#define ST_FLOATS 36
#define ST_OP     (128 * ST_FLOATS)
#define ST_BYTES  (2 * ST_OP * 4)
#define GEMM_SMEM (3 * ST_BYTES)

__device__ __forceinline__ void load_stage(
    uint32_t sbase, int stage, const uint32_t* __restrict__ A, int lda,
    const uint32_t* __restrict__ Bt, int K, int rowBase, int colBase,
    int k0, int M, int tid)
{
    uint32_t st = sbase + stage * ST_BYTES;
    #pragma unroll
    for (int p = 0; p < 4; p++) {
        int idx = tid + (p << 8);
        int row = idx >> 3;
        int kc  = idx & 7;
        uint32_t off = row * 144 + kc * 16;
        int gr = rowBase + row;
        int okA = (gr < M) ? 16 : 0;
        const uint32_t* ga = A + (size_t)(okA ? gr : 0) * lda + k0 + kc * 4;
        cp16(st + off, ga, okA);
        const uint32_t* gb = Bt + (size_t)(colBase + row) * K + k0 + kc * 4;
        cp16(st + ST_OP * 4 + off, gb, 16);
    }
    cp_commit();
}

template <bool RELU, bool WF32, bool WT32>
__global__ __launch_bounds__(256, 2)
void gemm_tc(const uint32_t* __restrict__ A, int lda,
             const uint32_t* __restrict__ Bt,
             const float* __restrict__ bias,
             float* __restrict__ C, int ldc,
             uint32_t* __restrict__ Ct, int ldct,
             int M, int K)
{
    extern __shared__ char sm[];
    const uint32_t sbase = smem_u32(sm);
    const int tid  = threadIdx.x;
    const int lane = tid & 31;
    const int w    = tid >> 5;
    const int gid  = lane >> 2;
    const int tig  = lane & 3;
    const int warpM = w >> 2;
    const int warpN = w & 3;
    const int rowBase = blockIdx.x * 128;
    const int colBase = blockIdx.y * 128;
    const int nCh = K >> 5;

    float acc[4][4][4];
    #pragma unroll
    for (int mt = 0; mt < 4; mt++)
        #pragma unroll
        for (int nt = 0; nt < 4; nt++)
            #pragma unroll
            for (int j = 0; j < 4; j++) acc[mt][nt][j] = 0.f;

    load_stage(sbase, 0, A, lda, Bt, K, rowBase, colBase, 0, M, tid);
    load_stage(sbase, 1, A, lda, Bt, K, rowBase, colBase, 32, M, tid);

    int stage = 0;
    #pragma unroll 1
    for (int c = 0; c < nCh; c++) {
        if (c + 1 < nCh) cp_wait<1>(); else cp_wait<0>();
        __syncthreads();
        if (c + 2 < nCh) {
            int ns = stage + 2; if (ns >= 3) ns -= 3;
            load_stage(sbase, ns, A, lda, Bt, K, rowBase, colBase, (c + 2) << 5, M, tid);
        }
        const uint32_t* sA = reinterpret_cast<const uint32_t*>(sm + stage * ST_BYTES);
        const uint32_t* sB = sA + ST_OP;
        #pragma unroll
        for (int kk = 0; kk < 4; kk++) {
            uint32_t af[4][4], bf[4][2];
            #pragma unroll
            for (int mt = 0; mt < 4; mt++) {
                const uint32_t* p = &sA[(warpM * 64 + mt * 16 + gid) * ST_FLOATS + kk * 8 + tig];
                af[mt][0] = p[0];
                af[mt][1] = p[8 * ST_FLOATS];
                af[mt][2] = p[4];
                af[mt][3] = p[8 * ST_FLOATS + 4];
            }
            #pragma unroll
            for (int nt = 0; nt < 4; nt++) {
                const uint32_t* p = &sB[(warpN * 32 + nt * 8 + gid) * ST_FLOATS + kk * 8 + tig];
                bf[nt][0] = p[0];
                bf[nt][1] = p[4];
            }
            #pragma unroll
            for (int mt = 0; mt < 4; mt++)
                #pragma unroll
                for (int nt = 0; nt < 4; nt++)
                    mma_tf32(acc[mt][nt], af[mt], bf[nt]);
        }
        stage++; if (stage >= 3) stage = 0;
    }

    #pragma unroll
    for (int mt = 0; mt < 4; mt++) {
        int r0 = rowBase + warpM * 64 + mt * 16 + gid;
        #pragma unroll
        for (int nt = 0; nt < 4; nt++) {
            int cc = colBase + warpN * 32 + nt * 8 + tig * 2;
            float2 bi = *reinterpret_cast<const float2*>(bias + cc);
            #pragma unroll
            for (int h = 0; h < 2; h++) {
                int r = r0 + h * 8;
                if (r < M) {
                    float ox = acc[mt][nt][h * 2 + 0] + bi.x;
                    float oy = acc[mt][nt][h * 2 + 1] + bi.y;
                    if (RELU) { ox = fmaxf(ox, 0.f); oy = fmaxf(oy, 0.f); }
                    if (WF32)
                        *reinterpret_cast<float2*>(C + (size_t)r * ldc + cc) = make_float2(ox, oy);
                    if (WT32) {
                        uint2 u = make_uint2(f2t(ox), f2t(oy));
                        *reinterpret_cast<uint2*>(Ct + (size_t)r * ldct + cc) = u;
                    }
                }
            }
        }
    }
}

// ---------------- fused prep: obs cvt + weight packs + deg zero -----------------
// block ranges: [0,6250) obs cvt; [6250,6506) W1; [6506,6762) W2;
// [6762,6826) qkv1; [6826,6890) qkv2; [6890,7086) zero g_deg
#define PREP_BLOCKS 7086

__global__ void k_prep(const float* __restrict__ obs,
                       const float* __restrict__ W1, const float* __restrict__ W2,
                       const float* __restrict__ Wq1, const float* __restrict__ bq1,
                       const float* __restrict__ Wk1, const float* __restrict__ bk1,
                       const float* __restrict__ Wv1, const float* __restrict__ bv1,
                       const float* __restrict__ Wq2, const float* __restrict__ bq2,
                       const float* __restrict__ Wk2, const float* __restrict__ bk2,
                       const float* __restrict__ Wv2, const float* __restrict__ bv2)
{
    int b = blockIdx.x, t = threadIdx.x;
    if (b < 6250) {
        int i = (b * 256 + t) * 4;
        if (i < N_NODES * OBS_DIM) {
            float4 v = *reinterpret_cast<const float4*>(obs + i);
            *reinterpret_cast<uint4*>(g_obsT + i) =
                make_uint4(f2t(v.x), f2t(v.y), f2t(v.z), f2t(v.w));
        }
    } else if (b < 6506) {
        int i = (b - 6250) * 256 + t;       // W1: [128,512] -> g_W1t [512][128]
        int k = i >> 9, n = i & 511;
        g_W1t[n * 128 + k] = f2t(W1[i]);
    } else if (b < 6762) {
        int i = (b - 6506) * 256 + t;       // W2: [512,128] -> g_W2t [128][512]
        int k = i >> 7, n = i & 127;
        g_W2t[n * 512 + k] = f2t(W2[i]);
    } else if (b < 6826) {
        int i = (b - 6762) * 256 + t;       // qkv1
        int k = i >> 7, n = i & 127;
        g_Wt1[n * 128 + k]         = f2t(Wq1[i]);
        g_Wt1[(n + 128) * 128 + k] = f2t(Wk1[i]);
        g_Wt1[(n + 256) * 128 + k] = f2t(Wv1[i]);
        if (i < 128) { g_bp1[i] = bq1[i]; g_bp1[128 + i] = bk1[i]; g_bp1[256 + i] = bv1[i]; }
    } else if (b < 6890) {
        int i = (b - 6826) * 256 + t;       // qkv2
        int k = i >> 7, n = i & 127;
        g_Wt2[n * 128 + k]         = f2t(Wq2[i]);
        g_Wt2[(n + 128) * 128 + k] = f2t(Wk2[i]);
        g_Wt2[(n + 256) * 128 + k] = f2t(Wv2[i]);
        if (i < 128) { g_bp2[i] = bq2[i]; g_bp2[128 + i] = bk2[i]; g_bp2[256 + i] = bv2[i]; }
    } else {
        int i = (b - 6890) * 256 + t;       // zero degrees
        if (i < N_NODES) g_deg[i] = 0;
    }
}

// ---------------- CSR build -----------------------------------------------------
__global__ void k_count(const int* __restrict__ dst) {
    int e = blockIdx.x * blockDim.x + threadIdx.x;
    if (e < N_EDGES) atomicAdd(&g_deg[dst[e]], 1);
}

__device__ __forceinline__ int block_excl_scan(int v, int tid) {
    int lane = tid & 31, w = tid >> 5;
    int x = v;
    #pragma unroll
    for (int d = 1; d < 32; d <<= 1) {
        int t = __shfl_up_sync(0xffffffffu, x, d);
        if (lane >= d) x += t;
    }
    __shared__ int ws[8];
    if (lane == 31) ws[w] = x;
    __syncthreads();
    if (w == 0) {
        int y = (lane < 8) ? ws[lane] : 0;
        #pragma unroll
        for (int d = 1; d < 8; d <<= 1) {
            int t = __shfl_up_sync(0xffffffffu, y, d);
            if (lane >= d) y += t;
        }
        if (lane < 8) ws[lane] = y;
    }
    __syncthreads();
    return x - v + ((w > 0) ? ws[w - 1] : 0);
}

__global__ void k_scan1() {
    int tid = threadIdx.x;
    int i = blockIdx.x * 256 + tid;
    int v = (i < N_NODES) ? g_deg[i] : 0;
    int excl = block_excl_scan(v, tid);
    if (i < N_NODES) g_off[i] = excl;
    if (tid == 255) g_bsum[blockIdx.x] = excl + v;
}

__global__ void k_scan2() {
    int tid = threadIdx.x;
    int v = (tid < NB_SCAN) ? g_bsum[tid] : 0;
    int excl = block_excl_scan(v, tid);
    if (tid < NB_SCAN) g_bsum[tid] = excl;
    if (tid == NB_SCAN - 1) g_off[N_NODES] = excl + v;
}

__global__ void k_scan3() {
    int i = blockIdx.x * 256 + threadIdx.x;
    if (i < N_NODES) {
        int o = g_off[i] + g_bsum[blockIdx.x];
        g_off[i] = o;
        g_pos[i] = o;
    }
}

__global__ void k_scatter(const int* __restrict__ src, const int* __restrict__ dst) {
    int e = blockIdx.x * blockDim.x + threadIdx.x;
    if (e < N_EDGES) {
        int d = dst[e];
        int idx = atomicAdd(&g_pos[d], 1);
        g_srcs[idx] = src[e];
    }
}

// ---------------- GAT: one warp per dst node, dual-state online softmax ---------
template <bool WT32>
__global__ void k_gat(const float* __restrict__ qkv, float* __restrict__ zout, int ldz,
                      uint32_t* __restrict__ xt)
{
    int node = (blockIdx.x * blockDim.x + threadIdx.x) >> 5;
    int lane = threadIdx.x & 31;
    if (node >= N_NODES) return;

    const float4 qv = *reinterpret_cast<const float4*>(qkv + (size_t)node * QKV_LD + lane * 4);

    float mA = -1e30f, sA = 0.f, axA = 0.f, ayA = 0.f, azA = 0.f, awA = 0.f;
    float mB = -1e30f, sB = 0.f, axB = 0.f, ayB = 0.f, azB = 0.f, awB = 0.f;

    int t = g_off[node], end = g_off[node + 1];
    while (t < end) {
        int nload = min(32, end - t);
        int sj = (lane < nload) ? __ldg(&g_srcs[t + lane]) : 0;
        int j = 0;
        for (; j + 1 < nload; j += 2) {
            int s0 = __shfl_sync(0xffffffffu, sj, j);
            int s1 = __shfl_sync(0xffffffffu, sj, j + 1);
            const float* b0 = qkv + (size_t)s0 * QKV_LD;
            const float* b1 = qkv + (size_t)s1 * QKV_LD;
            const float4 k0 = *reinterpret_cast<const float4*>(b0 + 128 + lane * 4);
            const float4 v0 = *reinterpret_cast<const float4*>(b0 + 256 + lane * 4);
            const float4 k1 = *reinterpret_cast<const float4*>(b1 + 128 + lane * 4);
            const float4 v1 = *reinterpret_cast<const float4*>(b1 + 256 + lane * 4);

            float p0 = qv.x * k0.x + qv.y * k0.y + qv.z * k0.z + qv.w * k0.w;
            float p1 = qv.x * k1.x + qv.y * k1.y + qv.z * k1.z + qv.w * k1.w;
            p0 += __shfl_xor_sync(0xffffffffu, p0, 1);
            p1 += __shfl_xor_sync(0xffffffffu, p1, 1);
            p0 += __shfl_xor_sync(0xffffffffu, p0, 2);
            p1 += __shfl_xor_sync(0xffffffffu, p1, 2);
            float sc0 = p0 * 0.25f, sc1 = p1 * 0.25f;

            float mn0 = fmaxf(mA, sc0);
            float mn1 = fmaxf(mB, sc1);
            float c0 = __expf(mA - mn0), w0 = __expf(sc0 - mn0);
            float c1 = __expf(mB - mn1), w1 = __expf(sc1 - mn1);
            sA = sA * c0 + w0;
            sB = sB * c1 + w1;
            axA = axA * c0 + w0 * v0.x;  axB = axB * c1 + w1 * v1.x;
            ayA = ayA * c0 + w0 * v0.y;  ayB = ayB * c1 + w1 * v1.y;
            azA = azA * c0 + w0 * v0.z;  azB = azB * c1 + w1 * v1.z;
            awA = awA * c0 + w0 * v0.w;  awB = awB * c1 + w1 * v1.w;
            mA = mn0; mB = mn1;
        }
        if (j < nload) {
            int s0 = __shfl_sync(0xffffffffu, sj, j);
            const float* b0 = qkv + (size_t)s0 * QKV_LD;
            const float4 k0 = *reinterpret_cast<const float4*>(b0 + 128 + lane * 4);
            const float4 v0 = *reinterpret_cast<const float4*>(b0 + 256 + lane * 4);
            float p0 = qv.x * k0.x + qv.y * k0.y + qv.z * k0.z + qv.w * k0.w;
            p0 += __shfl_xor_sync(0xffffffffu, p0, 1);
            p0 += __shfl_xor_sync(0xffffffffu, p0, 2);
            float sc0 = p0 * 0.25f;
            float mn0 = fmaxf(mA, sc0);
            float c0 = __expf(mA - mn0), w0 = __expf(sc0 - mn0);
            sA = sA * c0 + w0;
            axA = axA * c0 + w0 * v0.x;
            ayA = ayA * c0 + w0 * v0.y;
            azA = azA * c0 + w0 * v0.z;
            awA = awA * c0 + w0 * v0.w;
            mA = mn0;
        }
        t += nload;
    }

    // merge states
    float m = fmaxf(mA, mB);
    float cA = __expf(mA - m), cB = __expf(mB - m);
    float sum = sA * cA + sB * cB;
    float ax = axA * cA + axB * cB;
    float ay = ayA * cA + ayB * cB;
    float az = azA * cA + azB * cB;
    float aw = awA * cA + awB * cB;

    float inv = 1.f / (sum + 1e-9f);
    float4 o;
    o.x = fmaxf(ax * inv, 0.f);
    o.y = fmaxf(ay * inv, 0.f);
    o.z = fmaxf(az * inv, 0.f);
    o.w = fmaxf(aw * inv, 0.f);
    *reinterpret_cast<float4*>(zout + (size_t)node * ldz + lane * 4) = o;
    if (WT32) {
        uint4 u = make_uint4(f2t(o.x), f2t(o.y), f2t(o.z), f2t(o.w));
        *reinterpret_cast<uint4*>(xt + (size_t)node * H_DIM + lane * 4) = u;
    }
}

// ---------------- host ----------------------------------------------------------
extern "C" void kernel_launch(void* const* d_in, const int* in_sizes, int n_in,
                              void* d_out, int out_size)
{
    const float* obs = (const float*)d_in[0];
    const int*   src = (const int*)d_in[1];
    const int*   dst = (const int*)d_in[2];
    const float* W1  = (const float*)d_in[3];  const float* b1  = (const float*)d_in[4];
    const float* W2  = (const float*)d_in[5];  const float* b2  = (const float*)d_in[6];
    const float* Wq1 = (const float*)d_in[7];  const float* bq1 = (const float*)d_in[8];
    const float* Wk1 = (const float*)d_in[9];  const float* bk1 = (const float*)d_in[10];
    const float* Wv1 = (const float*)d_in[11]; const float* bv1 = (const float*)d_in[12];
    const float* Wq2 = (const float*)d_in[13]; const float* bq2 = (const float*)d_in[14];
    const float* Wk2 = (const float*)d_in[15]; const float* bk2 = (const float*)d_in[16];
    const float* Wv2 = (const float*)d_in[17]; const float* bv2 = (const float*)d_in[18];
    float* out = (float*)d_out;

    uint32_t *p_obsT, *p_h1, *p_xt, *p_W1t, *p_W2t, *p_Wt1, *p_Wt2;
    float *p_qkv, *p_bp1, *p_bp2;
    cudaGetSymbolAddress((void**)&p_obsT, g_obsT);
    cudaGetSymbolAddress((void**)&p_h1,   g_h1);
    cudaGetSymbolAddress((void**)&p_xt,   g_xt);
    cudaGetSymbolAddress((void**)&p_qkv,  g_qkv);
    cudaGetSymbolAddress((void**)&p_W1t,  g_W1t);
    cudaGetSymbolAddress((void**)&p_W2t,  g_W2t);
    cudaGetSymbolAddress((void**)&p_Wt1,  g_Wt1);
    cudaGetSymbolAddress((void**)&p_Wt2,  g_Wt2);
    cudaGetSymbolAddress((void**)&p_bp1,  g_bp1);
    cudaGetSymbolAddress((void**)&p_bp2,  g_bp2);

    cudaFuncSetAttribute(gemm_tc<true, false, true>,  cudaFuncAttributeMaxDynamicSharedMemorySize, GEMM_SMEM);
    cudaFuncSetAttribute(gemm_tc<true, true, true>,   cudaFuncAttributeMaxDynamicSharedMemorySize, GEMM_SMEM);
    cudaFuncSetAttribute(gemm_tc<false, true, false>, cudaFuncAttributeMaxDynamicSharedMemorySize, GEMM_SMEM);

    const int MT = (N_NODES + 127) / 128;   // 391

    // prep (includes g_deg zeroing)
    k_prep<<<PREP_BLOCKS, 256>>>(obs, W1, W2,
                                 Wq1, bq1, Wk1, bk1, Wv1, bv1,
                                 Wq2, bq2, Wk2, bk2, Wv2, bv2);

    // CSR build
    k_count<<<(N_EDGES + 255) / 256, 256>>>(dst);
    k_scan1<<<NB_SCAN, 256>>>();
    k_scan2<<<1, 256>>>();
    k_scan3<<<NB_SCAN, 256>>>();
    k_scatter<<<(N_EDGES + 255) / 256, 256>>>(src, dst);

    // MLP encoder
    gemm_tc<true, false, true><<<dim3(MT, ENC_H / 128), 256, GEMM_SMEM>>>(
        p_obsT, OBS_DIM, p_W1t, b1, nullptr, 0, p_h1, ENC_H, N_NODES, OBS_DIM);
    gemm_tc<true, true, true><<<dim3(MT, 1), 256, GEMM_SMEM>>>(
        p_h1, ENC_H, p_W2t, b2, out + 0, OUT_LD, p_xt, H_DIM, N_NODES, ENC_H);

    // GAT layer 1
    gemm_tc<false, true, false><<<dim3(MT, 3), 256, GEMM_SMEM>>>(
        p_xt, H_DIM, p_Wt1, p_bp1, p_qkv, QKV_LD, nullptr, 0, N_NODES, H_DIM);
    k_gat<true><<<(N_NODES * 32 + 255) / 256, 256>>>(p_qkv, out + H_DIM, OUT_LD, p_xt);

    // GAT layer 2
    gemm_tc<false, true, false><<<dim3(MT, 3), 256, GEMM_SMEM>>>(
        p_xt, H_DIM, p_Wt2, p_bp2, p_qkv, QKV_LD, nullptr, 0, N_NODES, H_DIM);
    k_gat<false><<<(N_NODES * 32 + 255) / 256, 256>>>(p_qkv, out + 2 * H_DIM, OUT_LD, nullptr);
}

// round 7
// speedup vs baseline: 3.1907x; 1.0854x over previous
#include <cuda_runtime.h>
#include <cuda_fp16.h>
#include <cstdint>
#include <math.h>

#define N_NODES 50000
#define N_EDGES 800000
#define OBS_DIM 128
#define H_DIM   128
#define ENC_H   512
#define OUT_LD  384
#define NB_SCAN 196   // ceil(50000/256)

// ---------------- scratch ------------------------------------------------------
__device__ uint32_t g_obsT[(size_t)N_NODES * OBS_DIM];  // tf32 obs
__device__ uint32_t g_h1[(size_t)N_NODES * ENC_H];      // tf32 MLP hidden
__device__ uint32_t g_xt[(size_t)N_NODES * H_DIM];      // tf32 current x (GEMM A)
__device__ float    g_q [(size_t)N_NODES * H_DIM];      // fp32 q
__device__ __half   g_kv[(size_t)N_NODES * 256];        // fp16 k|v packed per node
__device__ uint32_t g_W1t[512 * 128];                   // tf32 [N,K] weights
__device__ uint32_t g_W2t[128 * 512];
__device__ uint32_t g_Wt1[384 * 128];
__device__ uint32_t g_Wt2[384 * 128];
__device__ float    g_bp1[384];
__device__ float    g_bp2[384];
__device__ int      g_deg[N_NODES];
__device__ int      g_off[N_NODES + 1];
__device__ int      g_pos[N_NODES];
__device__ int      g_srcs[N_EDGES];
__device__ unsigned long long g_lb[NB_SCAN];            // lookback state|value

#define LB_PARTIAL (1ull << 62)
#define LB_PREFIX  (2ull << 62)
#define LB_MASK    (3ull << 62)

// ---------------- helpers ------------------------------------------------------
__device__ __forceinline__ uint32_t f2t(float x) {
    uint32_t r;
    asm volatile("cvt.rna.tf32.f32 %0, %1;" : "=r"(r) : "f"(x));
    return r;
}
__device__ __forceinline__ uint32_t smem_u32(const void* p) {
    uint32_t a;
    asm("{ .reg .u64 t; cvta.to.shared.u64 t, %1; cvt.u32.u64 %0, t; }" : "=r"(a) : "l"(p));
    return a;
}
__device__ __forceinline__ void cp16(uint32_t sm_addr, const void* g, int nbytes) {
    asm volatile("cp.async.cg.shared.global [%0], [%1], 16, %2;"
                 :: "r"(sm_addr), "l"(g), "r"(nbytes) : "memory");
}
__device__ __forceinline__ void cp_commit() {
    asm volatile("cp.async.commit_group;" ::: "memory");
}
template <int N>
__device__ __forceinline__ void cp_wait() {
    asm volatile("cp.async.wait_group %0;" :: "n"(N) : "memory");
}
__device__ __forceinline__ void mma_tf32(float* c, const uint32_t* a, const uint32_t* b) {
    asm volatile(
        "mma.sync.aligned.m16n8k8.row.col.f32.tf32.tf32.f32 "
        "{%0,%1,%2,%3}, {%4,%5,%6,%7}, {%8,%9}, {%0,%1,%2,%3};\n"
        : "+f"(c[0]), "+f"(c[1]), "+f"(c[2]), "+f"(c[3])
        : "r"(a[0]), "r"(a[1]), "r"(a[2]), "r"(a[3]), "r"(b[0]), "r"(b[1]));
}

// ---------------- pipelined TF32 GEMM -------------------------------------------
// Modes: 0 = tf32 out only (+relu, ldct) ; 1 = fp32 out (ldc) + tf32 xt (+relu) ;
//        2 = qkv: slab0 -> g_q fp32, slabs1/2 -> g_kv fp16 (no relu)
#define ST_FLOATS 36
#define ST_OP     (128 * ST_FLOATS)
#define ST_BYTES  (2 * ST_OP * 4)
#define GEMM_SMEM (3 * ST_BYTES)

__device__ __forceinline__ void load_stage(
    uint32_t sbase, int stage, const uint32_t* __restrict__ A, int lda,
    const uint32_t* __restrict__ Bt, int K, int rowBase, int colBase,
    int k0, int M, int tid)
{
    uint32_t st = sbase + stage * ST_BYTES;
    #pragma unroll
    for (int p = 0; p < 4; p++) {
        int idx = tid + (p << 8);
        int row = idx >> 3;
        int kc  = idx & 7;
        uint32_t off = row * 144 + kc * 16;
        int gr = rowBase + row;
        int okA = (gr < M) ? 16 : 0;
        const uint32_t* ga = A + (size_t)(okA ? gr : 0) * lda + k0 + kc * 4;
        cp16(st + off, ga, okA);
        const uint32_t* gb = Bt + (size_t)(colBase + row) * K + k0 + kc * 4;
        cp16(st + ST_OP * 4 + off, gb, 16);
    }
    cp_commit();
}

template <int MODE>
__global__ __launch_bounds__(256, 2)
void gemm_tc(const uint32_t* __restrict__ A, int lda,
             const uint32_t* __restrict__ Bt,
             const float* __restrict__ bias,
             float* __restrict__ C, int ldc,
             uint32_t* __restrict__ Ct, int ldct,
             int M, int K)
{
    extern __shared__ char sm[];
    const uint32_t sbase = smem_u32(sm);
    const int tid  = threadIdx.x;
    const int lane = tid & 31;
    const int w    = tid >> 5;
    const int gid  = lane >> 2;
    const int tig  = lane & 3;
    const int warpM = w >> 2;
    const int warpN = w & 3;
    const int rowBase = blockIdx.x * 128;
    const int colBase = blockIdx.y * 128;
    const int nCh = K >> 5;

    float acc[4][4][4];
    #pragma unroll
    for (int mt = 0; mt < 4; mt++)
        #pragma unroll
        for (int nt = 0; nt < 4; nt++)
            #pragma unroll
            for (int j = 0; j < 4; j++) acc[mt][nt][j] = 0.f;

    load_stage(sbase, 0, A, lda, Bt, K, rowBase, colBase, 0, M, tid);
    load_stage(sbase, 1, A, lda, Bt, K, rowBase, colBase, 32, M, tid);

    int stage = 0;
    #pragma unroll 1
    for (int c = 0; c < nCh; c++) {
        if (c + 1 < nCh) cp_wait<1>(); else cp_wait<0>();
        __syncthreads();
        if (c + 2 < nCh) {
            int ns = stage + 2; if (ns >= 3) ns -= 3;
            load_stage(sbase, ns, A, lda, Bt, K, rowBase, colBase, (c + 2) << 5, M, tid);
        }
        const uint32_t* sA = reinterpret_cast<const uint32_t*>(sm + stage * ST_BYTES);
        const uint32_t* sB = sA + ST_OP;
        #pragma unroll
        for (int kk = 0; kk < 4; kk++) {
            uint32_t af[4][4], bf[4][2];
            #pragma unroll
            for (int mt = 0; mt < 4; mt++) {
                const uint32_t* p = &sA[(warpM * 64 + mt * 16 + gid) * ST_FLOATS + kk * 8 + tig];
                af[mt][0] = p[0];
                af[mt][1] = p[8 * ST_FLOATS];
                af[mt][2] = p[4];
                af[mt][3] = p[8 * ST_FLOATS + 4];
            }
            #pragma unroll
            for (int nt = 0; nt < 4; nt++) {
                const uint32_t* p = &sB[(warpN * 32 + nt * 8 + gid) * ST_FLOATS + kk * 8 + tig];
                bf[nt][0] = p[0];
                bf[nt][1] = p[4];
            }
            #pragma unroll
            for (int mt = 0; mt < 4; mt++)
                #pragma unroll
                for (int nt = 0; nt < 4; nt++)
                    mma_tf32(acc[mt][nt], af[mt], bf[nt]);
        }
        stage++; if (stage >= 3) stage = 0;
    }

    #pragma unroll
    for (int mt = 0; mt < 4; mt++) {
        int r0 = rowBase + warpM * 64 + mt * 16 + gid;
        #pragma unroll
        for (int nt = 0; nt < 4; nt++) {
            int cc = colBase + warpN * 32 + nt * 8 + tig * 2;
            float2 bi = *reinterpret_cast<const float2*>(bias + cc);
            #pragma unroll
            for (int h = 0; h < 2; h++) {
                int r = r0 + h * 8;
                if (r < M) {
                    float ox = acc[mt][nt][h * 2 + 0] + bi.x;
                    float oy = acc[mt][nt][h * 2 + 1] + bi.y;
                    if (MODE != 2) { ox = fmaxf(ox, 0.f); oy = fmaxf(oy, 0.f); }
                    if (MODE == 0) {
                        uint2 u = make_uint2(f2t(ox), f2t(oy));
                        *reinterpret_cast<uint2*>(Ct + (size_t)r * ldct + cc) = u;
                    } else if (MODE == 1) {
                        *reinterpret_cast<float2*>(C + (size_t)r * ldc + cc) = make_float2(ox, oy);
                        uint2 u = make_uint2(f2t(ox), f2t(oy));
                        *reinterpret_cast<uint2*>(Ct + (size_t)r * ldct + cc) = u;
                    } else {
                        if (colBase == 0) {
                            *reinterpret_cast<float2*>(g_q + (size_t)r * H_DIM + cc) =
                                make_float2(ox, oy);
                        } else {
                            *reinterpret_cast<__half2*>(g_kv + (size_t)r * 256 + (cc - 128)) =
                                __floats2half2_rn(ox, oy);
                        }
                    }
                }
            }
        }
    }
}

// ---------------- fused prep: obs cvt + weight packs + zeroing ------------------
// block ranges: [0,6250) obs cvt; [6250,6506) W1; [6506,6762) W2;
// [6762,6826) qkv1; [6826,6890) qkv2; [6890,7086) zero g_deg + g_lb
#define PREP_BLOCKS 7086

__global__ void k_prep(const float* __restrict__ obs,
                       const float* __restrict__ W1, const float* __restrict__ W2,
                       const float* __restrict__ Wq1, const float* __restrict__ bq1,
                       const float* __restrict__ Wk1, const float* __restrict__ bk1,
                       const float* __restrict__ Wv1, const float* __restrict__ bv1,
                       const float* __restrict__ Wq2, const float* __restrict__ bq2,
                       const float* __restrict__ Wk2, const float* __restrict__ bk2,
                       const float* __restrict__ Wv2, const float* __restrict__ bv2)
{
    int b = blockIdx.x, t = threadIdx.x;
    if (b < 6250) {
        int i = (b * 256 + t) * 4;
        if (i < N_NODES * OBS_DIM) {
            float4 v = *reinterpret_cast<const float4*>(obs + i);
            *reinterpret_cast<uint4*>(g_obsT + i) =
                make_uint4(f2t(v.x), f2t(v.y), f2t(v.z), f2t(v.w));
        }
    } else if (b < 6506) {
        int i = (b - 6250) * 256 + t;       // W1: [128,512] -> g_W1t [512][128]
        int k = i >> 9, n = i & 511;
        g_W1t[n * 128 + k] = f2t(W1[i]);
    } else if (b < 6762) {
        int i = (b - 6506) * 256 + t;       // W2: [512,128] -> g_W2t [128][512]
        int k = i >> 7, n = i & 127;
        g_W2t[n * 512 + k] = f2t(W2[i]);
    } else if (b < 6826) {
        int i = (b - 6762) * 256 + t;       // qkv1
        int k = i >> 7, n = i & 127;
        g_Wt1[n * 128 + k]         = f2t(Wq1[i]);
        g_Wt1[(n + 128) * 128 + k] = f2t(Wk1[i]);
        g_Wt1[(n + 256) * 128 + k] = f2t(Wv1[i]);
        if (i < 128) { g_bp1[i] = bq1[i]; g_bp1[128 + i] = bk1[i]; g_bp1[256 + i] = bv1[i]; }
    } else if (b < 6890) {
        int i = (b - 6826) * 256 + t;       // qkv2
        int k = i >> 7, n = i & 127;
        g_Wt2[n * 128 + k]         = f2t(Wq2[i]);
        g_Wt2[(n + 128) * 128 + k] = f2t(Wk2[i]);
        g_Wt2[(n + 256) * 128 + k] = f2t(Wv2[i]);
        if (i < 128) { g_bp2[i] = bq2[i]; g_bp2[128 + i] = bk2[i]; g_bp2[256 + i] = bv2[i]; }
    } else {
        int i = (b - 6890) * 256 + t;       // zero degrees + lookback states
        if (i < N_NODES) g_deg[i] = 0;
        if (i < NB_SCAN) g_lb[i] = 0ull;
    }
}

// ---------------- CSR build -----------------------------------------------------
__global__ void k_count(const int* __restrict__ dst) {
    int e = blockIdx.x * blockDim.x + threadIdx.x;
    if (e < N_EDGES) atomicAdd(&g_deg[dst[e]], 1);
}

__device__ __forceinline__ int block_excl_scan(int v, int tid) {
    int lane = tid & 31, w = tid >> 5;
    int x = v;
    #pragma unroll
    for (int d = 1; d < 32; d <<= 1) {
        int t = __shfl_up_sync(0xffffffffu, x, d);
        if (lane >= d) x += t;
    }
    __shared__ int ws[8];
    if (lane == 31) ws[w] = x;
    __syncthreads();
    if (w == 0) {
        int y = (lane < 8) ? ws[lane] : 0;
        #pragma unroll
        for (int d = 1; d < 8; d <<= 1) {
            int t = __shfl_up_sync(0xffffffffu, y, d);
            if (lane >= d) y += t;
        }
        if (lane < 8) ws[lane] = y;
    }
    __syncthreads();
    return x - v + ((w > 0) ? ws[w - 1] : 0);
}

// single-pass decoupled-lookback scan: g_deg -> g_off/g_pos (+total)
__global__ void k_scan_lb() {
    int b = blockIdx.x, tid = threadIdx.x;
    int i = b * 256 + tid;
    int v = (i < N_NODES) ? g_deg[i] : 0;
    int excl = block_excl_scan(v, tid);
    __shared__ int s_prefix;

    if (tid == 255) {
        unsigned long long agg = (unsigned long long)(excl + v);
        if (b == 0) atomicExch(&g_lb[0], LB_PREFIX | agg);
        else        atomicExch(&g_lb[b], LB_PARTIAL | agg);
    }
    if (tid == 0) {
        if (b == 0) s_prefix = 0;
        else {
            long long running = 0;
            int p = b - 1;
            for (;;) {
                unsigned long long x = atomicAdd(&g_lb[p], 0ull);
                unsigned long long st = x & LB_MASK;
                if (st == LB_PREFIX)  { running += (long long)(x & ~LB_MASK); break; }
                if (st == LB_PARTIAL) { running += (long long)(x & ~LB_MASK); p--; }
            }
            s_prefix = (int)running;
        }
    }
    __syncthreads();
    int pre = s_prefix;
    if (b > 0 && tid == 255)
        atomicExch(&g_lb[b], LB_PREFIX | (unsigned long long)(pre + excl + v));
    if (i < N_NODES) {
        int o = pre + excl;
        g_off[i] = o;
        g_pos[i] = o;
    }
    if (b == NB_SCAN - 1 && tid == 255) g_off[N_NODES] = pre + excl + v;
}

__global__ void k_scatter(const int* __restrict__ src, const int* __restrict__ dst) {
    int e = blockIdx.x * blockDim.x + threadIdx.x;
    if (e < N_EDGES) {
        int d = dst[e];
        int idx = atomicAdd(&g_pos[d], 1);
        g_srcs[idx] = src[e];
    }
}

// ---------------- GAT: one warp per dst node, fp16 k/v, dual-state softmax ------
template <bool WT32>
__global__ void k_gat(float* __restrict__ zout, int ldz)
{
    int node = (blockIdx.x * blockDim.x + threadIdx.x) >> 5;
    int lane = threadIdx.x & 31;
    if (node >= N_NODES) return;

    const float4 qv = *reinterpret_cast<const float4*>(g_q + (size_t)node * H_DIM + lane * 4);

    float mA = -1e30f, sA = 0.f, axA = 0.f, ayA = 0.f, azA = 0.f, awA = 0.f;
    float mB = -1e30f, sB = 0.f, axB = 0.f, ayB = 0.f, azB = 0.f, awB = 0.f;

    int t = g_off[node], end = g_off[node + 1];
    while (t < end) {
        int nload = min(32, end - t);
        int sj = (lane < nload) ? __ldg(&g_srcs[t + lane]) : 0;
        int j = 0;
        for (; j + 1 < nload; j += 2) {
            int s0 = __shfl_sync(0xffffffffu, sj, j);
            int s1 = __shfl_sync(0xffffffffu, sj, j + 1);
            const uint2* kv0 = reinterpret_cast<const uint2*>(g_kv + (size_t)s0 * 256);
            const uint2* kv1 = reinterpret_cast<const uint2*>(g_kv + (size_t)s1 * 256);
            uint2 k0u = kv0[lane],      k1u = kv1[lane];
            uint2 v0u = kv0[32 + lane], v1u = kv1[32 + lane];

            float2 k0a = __half22float2(*reinterpret_cast<__half2*>(&k0u.x));
            float2 k0b = __half22float2(*reinterpret_cast<__half2*>(&k0u.y));
            float2 k1a = __half22float2(*reinterpret_cast<__half2*>(&k1u.x));
            float2 k1b = __half22float2(*reinterpret_cast<__half2*>(&k1u.y));

            float p0 = qv.x * k0a.x + qv.y * k0a.y + qv.z * k0b.x + qv.w * k0b.y;
            float p1 = qv.x * k1a.x + qv.y * k1a.y + qv.z * k1b.x + qv.w * k1b.y;
            p0 += __shfl_xor_sync(0xffffffffu, p0, 1);
            p1 += __shfl_xor_sync(0xffffffffu, p1, 1);
            p0 += __shfl_xor_sync(0xffffffffu, p0, 2);
            p1 += __shfl_xor_sync(0xffffffffu, p1, 2);
            float sc0 = p0 * 0.25f, sc1 = p1 * 0.25f;

            float2 v0a = __half22float2(*reinterpret_cast<__half2*>(&v0u.x));
            float2 v0b = __half22float2(*reinterpret_cast<__half2*>(&v0u.y));
            float2 v1a = __half22float2(*reinterpret_cast<__half2*>(&v1u.x));
            float2 v1b = __half22float2(*reinterpret_cast<__half2*>(&v1u.y));

            float mn0 = fmaxf(mA, sc0);
            float mn1 = fmaxf(mB, sc1);
            float c0 = __expf(mA - mn0), w0 = __expf(sc0 - mn0);
            float c1 = __expf(mB - mn1), w1 = __expf(sc1 - mn1);
            sA = sA * c0 + w0;
            sB = sB * c1 + w1;
            axA = axA * c0 + w0 * v0a.x;  axB = axB * c1 + w1 * v1a.x;
            ayA = ayA * c0 + w0 * v0a.y;  ayB = ayB * c1 + w1 * v1a.y;
            azA = azA * c0 + w0 * v0b.x;  azB = azB * c1 + w1 * v1b.x;
            awA = awA * c0 + w0 * v0b.y;  awB = awB * c1 + w1 * v1b.y;
            mA = mn0; mB = mn1;
        }
        if (j < nload) {
            int s0 = __shfl_sync(0xffffffffu, sj, j);
            const uint2* kv0 = reinterpret_cast<const uint2*>(g_kv + (size_t)s0 * 256);
            uint2 k0u = kv0[lane];
            uint2 v0u = kv0[32 + lane];
            float2 k0a = __half22float2(*reinterpret_cast<__half2*>(&k0u.x));
            float2 k0b = __half22float2(*reinterpret_cast<__half2*>(&k0u.y));
            float p0 = qv.x * k0a.x + qv.y * k0a.y + qv.z * k0b.x + qv.w * k0b.y;
            p0 += __shfl_xor_sync(0xffffffffu, p0, 1);
            p0 += __shfl_xor_sync(0xffffffffu, p0, 2);
            float sc0 = p0 * 0.25f;
            float2 v0a = __half22float2(*reinterpret_cast<__half2*>(&v0u.x));
            float2 v0b = __half22float2(*reinterpret_cast<__half2*>(&v0u.y));
            float mn0 = fmaxf(mA, sc0);
            float c0 = __expf(mA - mn0), w0 = __expf(sc0 - mn0);
            sA = sA * c0 + w0;
            axA = axA * c0 + w0 * v0a.x;
            ayA = ayA * c0 + w0 * v0a.y;
            azA = azA * c0 + w0 * v0b.x;
            awA = awA * c0 + w0 * v0b.y;
            mA = mn0;
        }
        t += nload;
    }

    float m = fmaxf(mA, mB);
    float cA = __expf(mA - m), cB = __expf(mB - m);
    float sum = sA * cA + sB * cB;
    float ax = axA * cA + axB * cB;
    float ay = ayA * cA + ayB * cB;
    float az = azA * cA + azB * cB;
    float aw = awA * cA + awB * cB;

    float inv = 1.f / (sum + 1e-9f);
    float4 o;
    o.x = fmaxf(ax * inv, 0.f);
    o.y = fmaxf(ay * inv, 0.f);
    o.z = fmaxf(az * inv, 0.f);
    o.w = fmaxf(aw * inv, 0.f);
    *reinterpret_cast<float4*>(zout + (size_t)node * ldz + lane * 4) = o;
    if (WT32) {
        uint4 u = make_uint4(f2t(o.x), f2t(o.y), f2t(o.z), f2t(o.w));
        *reinterpret_cast<uint4*>(g_xt + (size_t)node * H_DIM + lane * 4) = u;
    }
}

// ---------------- host ----------------------------------------------------------
extern "C" void kernel_launch(void* const* d_in, const int* in_sizes, int n_in,
                              void* d_out, int out_size)
{
    const float* obs = (const float*)d_in[0];
    const int*   src = (const int*)d_in[1];
    const int*   dst = (const int*)d_in[2];
    const float* W1  = (const float*)d_in[3];  const float* b1  = (const float*)d_in[4];
    const float* W2  = (const float*)d_in[5];  const float* b2  = (const float*)d_in[6];
    const float* Wq1 = (const float*)d_in[7];  const float* bq1 = (const float*)d_in[8];
    const float* Wk1 = (const float*)d_in[9];  const float* bk1 = (const float*)d_in[10];
    const float* Wv1 = (const float*)d_in[11]; const float* bv1 = (const float*)d_in[12];
    const float* Wq2 = (const float*)d_in[13]; const float* bq2 = (const float*)d_in[14];
    const float* Wk2 = (const float*)d_in[15]; const float* bk2 = (const float*)d_in[16];
    const float* Wv2 = (const float*)d_in[17]; const float* bv2 = (const float*)d_in[18];
    float* out = (float*)d_out;

    uint32_t *p_obsT, *p_h1, *p_xt, *p_W1t, *p_W2t, *p_Wt1, *p_Wt2;
    float *p_bp1, *p_bp2;
    cudaGetSymbolAddress((void**)&p_obsT, g_obsT);
    cudaGetSymbolAddress((void**)&p_h1,   g_h1);
    cudaGetSymbolAddress((void**)&p_xt,   g_xt);
    cudaGetSymbolAddress((void**)&p_W1t,  g_W1t);
    cudaGetSymbolAddress((void**)&p_W2t,  g_W2t);
    cudaGetSymbolAddress((void**)&p_Wt1,  g_Wt1);
    cudaGetSymbolAddress((void**)&p_Wt2,  g_Wt2);
    cudaGetSymbolAddress((void**)&p_bp1,  g_bp1);
    cudaGetSymbolAddress((void**)&p_bp2,  g_bp2);

    cudaFuncSetAttribute(gemm_tc<0>, cudaFuncAttributeMaxDynamicSharedMemorySize, GEMM_SMEM);
    cudaFuncSetAttribute(gemm_tc<1>, cudaFuncAttributeMaxDynamicSharedMemorySize, GEMM_SMEM);
    cudaFuncSetAttribute(gemm_tc<2>, cudaFuncAttributeMaxDynamicSharedMemorySize, GEMM_SMEM);

    const int MT = (N_NODES + 127) / 128;   // 391

    // prep (includes zeroing of g_deg / g_lb)
    k_prep<<<PREP_BLOCKS, 256>>>(obs, W1, W2,
                                 Wq1, bq1, Wk1, bk1, Wv1, bv1,
                                 Wq2, bq2, Wk2, bk2, Wv2, bv2);

    // CSR build (3 launches)
    k_count<<<(N_EDGES + 255) / 256, 256>>>(dst);
    k_scan_lb<<<NB_SCAN, 256>>>();
    k_scatter<<<(N_EDGES + 255) / 256, 256>>>(src, dst);

    // MLP encoder
    gemm_tc<0><<<dim3(MT, ENC_H / 128), 256, GEMM_SMEM>>>(
        p_obsT, OBS_DIM, p_W1t, b1, nullptr, 0, p_h1, ENC_H, N_NODES, OBS_DIM);
    gemm_tc<1><<<dim3(MT, 1), 256, GEMM_SMEM>>>(
        p_h1, ENC_H, p_W2t, b2, out + 0, OUT_LD, p_xt, H_DIM, N_NODES, ENC_H);

    // GAT layer 1
    gemm_tc<2><<<dim3(MT, 3), 256, GEMM_SMEM>>>(
        p_xt, H_DIM, p_Wt1, p_bp1, nullptr, 0, nullptr, 0, N_NODES, H_DIM);
    k_gat<true><<<(N_NODES * 32 + 255) / 256, 256>>>(out + H_DIM, OUT_LD);

    // GAT layer 2
    gemm_tc<2><<<dim3(MT, 3), 256, GEMM_SMEM>>>(
        p_xt, H_DIM, p_Wt2, p_bp2, nullptr, 0, nullptr, 0, N_NODES, H_DIM);
    k_gat<false><<<(N_NODES * 32 + 255) / 256, 256>>>(out + 2 * H_DIM, OUT_LD);
}

// round 8
// speedup vs baseline: 3.8786x; 1.2156x over previous
#include <cuda_runtime.h>
#include <cuda_fp16.h>
#include <cstdint>
#include <math.h>

#define N_NODES 50000
#define N_EDGES 800000
#define OBS_DIM 128
#define H_DIM   128
#define ENC_H   512
#define OUT_LD  384
#define NB_SCAN 196   // ceil(50000/256)

// ---------------- scratch ------------------------------------------------------
__device__ __half   g_obsT[(size_t)N_NODES * OBS_DIM];  // fp16 obs
__device__ __half   g_h1[(size_t)N_NODES * ENC_H];      // fp16 MLP hidden
__device__ __half   g_xt[(size_t)N_NODES * H_DIM];      // fp16 current x (GEMM A)
__device__ float    g_q [(size_t)N_NODES * H_DIM];      // fp32 q
__device__ __half   g_kv[(size_t)N_NODES * 256];        // fp16 k|v packed per node
__device__ __half   g_W1t[512 * 128];                   // fp16 [N,K] weights
__device__ __half   g_W2t[128 * 512];
__device__ __half   g_Wt1[384 * 128];
__device__ __half   g_Wt2[384 * 128];
__device__ float    g_bp1[384];
__device__ float    g_bp2[384];
__device__ int      g_deg[N_NODES];
__device__ int      g_off[N_NODES + 1];
__device__ int      g_pos[N_NODES];
__device__ int      g_srcs[N_EDGES];
__device__ unsigned long long g_lb[NB_SCAN];            // lookback state|value

#define LB_PARTIAL (1ull << 62)
#define LB_PREFIX  (2ull << 62)
#define LB_MASK    (3ull << 62)

// ---------------- helpers ------------------------------------------------------
__device__ __forceinline__ uint32_t smem_u32(const void* p) {
    uint32_t a;
    asm("{ .reg .u64 t; cvta.to.shared.u64 t, %1; cvt.u32.u64 %0, t; }" : "=r"(a) : "l"(p));
    return a;
}
__device__ __forceinline__ void cp16(uint32_t sm_addr, const void* g, int nbytes) {
    asm volatile("cp.async.cg.shared.global [%0], [%1], 16, %2;"
                 :: "r"(sm_addr), "l"(g), "r"(nbytes) : "memory");
}
__device__ __forceinline__ void cp_commit() {
    asm volatile("cp.async.commit_group;" ::: "memory");
}
template <int N>
__device__ __forceinline__ void cp_wait() {
    asm volatile("cp.async.wait_group %0;" :: "n"(N) : "memory");
}
__device__ __forceinline__ void mma_f16(float* c, const uint32_t* a, const uint32_t* b) {
    asm volatile(
        "mma.sync.aligned.m16n8k16.row.col.f32.f16.f16.f32 "
        "{%0,%1,%2,%3}, {%4,%5,%6,%7}, {%8,%9}, {%0,%1,%2,%3};\n"
        : "+f"(c[0]), "+f"(c[1]), "+f"(c[2]), "+f"(c[3])
        : "r"(a[0]), "r"(a[1]), "r"(a[2]), "r"(a[3]), "r"(b[0]), "r"(b[1]));
}

// ---------------- pipelined FP16 GEMM -------------------------------------------
// C[M,N] = A[M,K] @ Bt^T (+bias); A half [M,K](lda), Bt half [Ntot,K].
// CTA tile 128x128, BK=32 halves, 3-stage cp.async. Row stride 40 halves (80 B).
// Modes: 0 = half out (+relu); 1 = fp32 out + half xt (+relu); 2 = qkv split.
#define SROW_U32 20                     // 80 B row stride in u32 units
#define ST_OP_B  (128 * 80)             // 10240 B per operand per stage
#define ST_BYTES (2 * ST_OP_B)          // 20480
#define GEMM_SMEM (3 * ST_BYTES)        // 61440

__device__ __forceinline__ void load_stage(
    uint32_t sbase, int stage, const __half* __restrict__ A, int lda,
    const __half* __restrict__ Bt, int K, int rowBase, int colBase,
    int k0, int M, int tid)
{
    uint32_t st = sbase + stage * ST_BYTES;
    #pragma unroll
    for (int p = 0; p < 2; p++) {
        int idx = tid + (p << 8);            // 0..511
        int row = idx >> 2;                  // 0..127
        int kc  = idx & 3;                   // 0..3 (16B = 8 halves each)
        uint32_t off = row * 80 + kc * 16;
        int gr = rowBase + row;
        int okA = (gr < M) ? 16 : 0;
        const __half* ga = A + (size_t)(okA ? gr : 0) * lda + k0 + kc * 8;
        cp16(st + off, ga, okA);
        const __half* gb = Bt + (size_t)(colBase + row) * K + k0 + kc * 8;
        cp16(st + ST_OP_B + off, gb, 16);
    }
    cp_commit();
}

template <int MODE>
__global__ __launch_bounds__(256, 2)
void gemm_tc(const __half* __restrict__ A, int lda,
             const __half* __restrict__ Bt,
             const float* __restrict__ bias,
             float* __restrict__ C, int ldc,
             __half* __restrict__ Ct, int ldct,
             int M, int K)
{
    extern __shared__ char sm[];
    const uint32_t sbase = smem_u32(sm);
    const int tid  = threadIdx.x;
    const int lane = tid & 31;
    const int w    = tid >> 5;
    const int gid  = lane >> 2;
    const int tig  = lane & 3;
    const int warpM = w >> 2;
    const int warpN = w & 3;
    const int rowBase = blockIdx.x * 128;
    const int colBase = blockIdx.y * 128;
    const int nCh = K >> 5;

    float acc[4][4][4];
    #pragma unroll
    for (int mt = 0; mt < 4; mt++)
        #pragma unroll
        for (int nt = 0; nt < 4; nt++)
            #pragma unroll
            for (int j = 0; j < 4; j++) acc[mt][nt][j] = 0.f;

    load_stage(sbase, 0, A, lda, Bt, K, rowBase, colBase, 0, M, tid);
    load_stage(sbase, 1, A, lda, Bt, K, rowBase, colBase, 32, M, tid);

    int stage = 0;
    #pragma unroll 1
    for (int c = 0; c < nCh; c++) {
        if (c + 1 < nCh) cp_wait<1>(); else cp_wait<0>();
        __syncthreads();
        if (c + 2 < nCh) {
            int ns = stage + 2; if (ns >= 3) ns -= 3;
            load_stage(sbase, ns, A, lda, Bt, K, rowBase, colBase, (c + 2) << 5, M, tid);
        }
        const uint32_t* sA = reinterpret_cast<const uint32_t*>(sm + stage * ST_BYTES);
        const uint32_t* sB = sA + ST_OP_B / 4;
        #pragma unroll
        for (int kk = 0; kk < 2; kk++) {
            uint32_t af[4][4], bf[4][2];
            #pragma unroll
            for (int mt = 0; mt < 4; mt++) {
                const uint32_t* p = &sA[(warpM * 64 + mt * 16 + gid) * SROW_U32 + kk * 8 + tig];
                af[mt][0] = p[0];
                af[mt][1] = p[8 * SROW_U32];
                af[mt][2] = p[4];
                af[mt][3] = p[8 * SROW_U32 + 4];
            }
            #pragma unroll
            for (int nt = 0; nt < 4; nt++) {
                const uint32_t* p = &sB[(warpN * 32 + nt * 8 + gid) * SROW_U32 + kk * 8 + tig];
                bf[nt][0] = p[0];
                bf[nt][1] = p[4];
            }
            #pragma unroll
            for (int mt = 0; mt < 4; mt++)
                #pragma unroll
                for (int nt = 0; nt < 4; nt++)
                    mma_f16(acc[mt][nt], af[mt], bf[nt]);
        }
        stage++; if (stage >= 3) stage = 0;
    }

    #pragma unroll
    for (int mt = 0; mt < 4; mt++) {
        int r0 = rowBase + warpM * 64 + mt * 16 + gid;
        #pragma unroll
        for (int nt = 0; nt < 4; nt++) {
            int cc = colBase + warpN * 32 + nt * 8 + tig * 2;
            float2 bi = *reinterpret_cast<const float2*>(bias + cc);
            #pragma unroll
            for (int h = 0; h < 2; h++) {
                int r = r0 + h * 8;
                if (r < M) {
                    float ox = acc[mt][nt][h * 2 + 0] + bi.x;
                    float oy = acc[mt][nt][h * 2 + 1] + bi.y;
                    if (MODE != 2) { ox = fmaxf(ox, 0.f); oy = fmaxf(oy, 0.f); }
                    if (MODE == 0) {
                        *reinterpret_cast<__half2*>(Ct + (size_t)r * ldct + cc) =
                            __floats2half2_rn(ox, oy);
                    } else if (MODE == 1) {
                        *reinterpret_cast<float2*>(C + (size_t)r * ldc + cc) = make_float2(ox, oy);
                        *reinterpret_cast<__half2*>(Ct + (size_t)r * ldct + cc) =
                            __floats2half2_rn(ox, oy);
                    } else {
                        if (colBase == 0) {
                            *reinterpret_cast<float2*>(g_q + (size_t)r * H_DIM + cc) =
                                make_float2(ox, oy);
                        } else {
                            *reinterpret_cast<__half2*>(g_kv + (size_t)r * 256 + (cc - 128)) =
                                __floats2half2_rn(ox, oy);
                        }
                    }
                }
            }
        }
    }
}

// ---------------- fused prep: obs cvt + weight packs + edge count ---------------
// block ranges: [0,6250) obs cvt; [6250,6506) W1; [6506,6762) W2;
// [6762,6826) qkv1; [6826,6890) qkv2; [6890,10015) edge count.
// g_deg is guaranteed zero on entry (zero-init at load; re-zeroed by k_scan_lb).
#define PREP_BLOCKS 10015

__global__ void k_prep(const float* __restrict__ obs, const int* __restrict__ dst,
                       const float* __restrict__ W1, const float* __restrict__ W2,
                       const float* __restrict__ Wq1, const float* __restrict__ bq1,
                       const float* __restrict__ Wk1, const float* __restrict__ bk1,
                       const float* __restrict__ Wv1, const float* __restrict__ bv1,
                       const float* __restrict__ Wq2, const float* __restrict__ bq2,
                       const float* __restrict__ Wk2, const float* __restrict__ bk2,
                       const float* __restrict__ Wv2, const float* __restrict__ bv2)
{
    int b = blockIdx.x, t = threadIdx.x;
    if (b < 6250) {
        int i = (b * 256 + t) * 4;
        if (i < N_NODES * OBS_DIM) {
            float4 v = *reinterpret_cast<const float4*>(obs + i);
            *reinterpret_cast<__half2*>(g_obsT + i)     = __floats2half2_rn(v.x, v.y);
            *reinterpret_cast<__half2*>(g_obsT + i + 2) = __floats2half2_rn(v.z, v.w);
        }
    } else if (b < 6506) {
        int i = (b - 6250) * 256 + t;       // W1: [128,512] -> g_W1t [512][128]
        int k = i >> 9, n = i & 511;
        g_W1t[n * 128 + k] = __float2half_rn(W1[i]);
    } else if (b < 6762) {
        int i = (b - 6506) * 256 + t;       // W2: [512,128] -> g_W2t [128][512]
        int k = i >> 7, n = i & 127;
        g_W2t[n * 512 + k] = __float2half_rn(W2[i]);
    } else if (b < 6826) {
        int i = (b - 6762) * 256 + t;       // qkv1
        int k = i >> 7, n = i & 127;
        g_Wt1[n * 128 + k]         = __float2half_rn(Wq1[i]);
        g_Wt1[(n + 128) * 128 + k] = __float2half_rn(Wk1[i]);
        g_Wt1[(n + 256) * 128 + k] = __float2half_rn(Wv1[i]);
        if (i < 128) { g_bp1[i] = bq1[i]; g_bp1[128 + i] = bk1[i]; g_bp1[256 + i] = bv1[i]; }
    } else if (b < 6890) {
        int i = (b - 6826) * 256 + t;       // qkv2
        int k = i >> 7, n = i & 127;
        g_Wt2[n * 128 + k]         = __float2half_rn(Wq2[i]);
        g_Wt2[(n + 128) * 128 + k] = __float2half_rn(Wk2[i]);
        g_Wt2[(n + 256) * 128 + k] = __float2half_rn(Wv2[i]);
        if (i < 128) { g_bp2[i] = bq2[i]; g_bp2[128 + i] = bk2[i]; g_bp2[256 + i] = bv2[i]; }
    } else {
        int e = (b - 6890) * 256 + t;       // edge degree count
        if (e < N_EDGES) atomicAdd(&g_deg[dst[e]], 1);
    }
}

// ---------------- CSR: single-pass decoupled-lookback scan ----------------------
__device__ __forceinline__ int block_excl_scan(int v, int tid) {
    int lane = tid & 31, w = tid >> 5;
    int x = v;
    #pragma unroll
    for (int d = 1; d < 32; d <<= 1) {
        int t = __shfl_up_sync(0xffffffffu, x, d);
        if (lane >= d) x += t;
    }
    __shared__ int ws[8];
    if (lane == 31) ws[w] = x;
    __syncthreads();
    if (w == 0) {
        int y = (lane < 8) ? ws[lane] : 0;
        #pragma unroll
        for (int d = 1; d < 8; d <<= 1) {
            int t = __shfl_up_sync(0xffffffffu, y, d);
            if (lane >= d) y += t;
        }
        if (lane < 8) ws[lane] = y;
    }
    __syncthreads();
    return x - v + ((w > 0) ? ws[w - 1] : 0);
}

__global__ void k_scan_lb() {
    int b = blockIdx.x, tid = threadIdx.x;
    int i = b * 256 + tid;
    int v = (i < N_NODES) ? g_deg[i] : 0;
    if (i < N_NODES) g_deg[i] = 0;          // reset for next call (invariant)
    int excl = block_excl_scan(v, tid);
    __shared__ int s_prefix;

    if (tid == 255) {
        unsigned long long agg = (unsigned long long)(excl + v);
        if (b == 0) atomicExch(&g_lb[0], LB_PREFIX | agg);
        else        atomicExch(&g_lb[b], LB_PARTIAL | agg);
    }
    if (tid == 0) {
        if (b == 0) s_prefix = 0;
        else {
            long long running = 0;
            int p = b - 1;
            for (;;) {
                unsigned long long x = atomicAdd(&g_lb[p], 0ull);
                unsigned long long st = x & LB_MASK;
                if (st == LB_PREFIX)  { running += (long long)(x & ~LB_MASK); break; }
                if (st == LB_PARTIAL) { running += (long long)(x & ~LB_MASK); p--; }
            }
            s_prefix = (int)running;
        }
    }
    __syncthreads();
    int pre = s_prefix;
    if (b > 0 && tid == 255)
        atomicExch(&g_lb[b], LB_PREFIX | (unsigned long long)(pre + excl + v));
    if (i < N_NODES) {
        int o = pre + excl;
        g_off[i] = o;
        g_pos[i] = o;
    }
    if (b == NB_SCAN - 1 && tid == 255) g_off[N_NODES] = pre + excl + v;
}

__global__ void k_scatter(const int* __restrict__ src, const int* __restrict__ dst) {
    int e = blockIdx.x * blockDim.x + threadIdx.x;
    if (e < NB_SCAN) g_lb[e] = 0ull;        // reset lookback for next call
    if (e < N_EDGES) {
        int d = dst[e];
        int idx = atomicAdd(&g_pos[d], 1);
        g_srcs[idx] = src[e];
    }
}

// ---------------- GAT: one warp per dst node, fp16 k/v, dual-state softmax ------
template <bool WXT>
__global__ void k_gat(float* __restrict__ zout, int ldz)
{
    int node = (blockIdx.x * blockDim.x + threadIdx.x) >> 5;
    int lane = threadIdx.x & 31;
    if (node >= N_NODES) return;

    const float4 qv = *reinterpret_cast<const float4*>(g_q + (size_t)node * H_DIM + lane * 4);

    float mA = -1e30f, sA = 0.f, axA = 0.f, ayA = 0.f, azA = 0.f, awA = 0.f;
    float mB = -1e30f, sB = 0.f, axB = 0.f, ayB = 0.f, azB = 0.f, awB = 0.f;

    int t = g_off[node], end = g_off[node + 1];
    while (t < end) {
        int nload = min(32, end - t);
        int sj = (lane < nload) ? __ldg(&g_srcs[t + lane]) : 0;
        int j = 0;
        for (; j + 1 < nload; j += 2) {
            int s0 = __shfl_sync(0xffffffffu, sj, j);
            int s1 = __shfl_sync(0xffffffffu, sj, j + 1);
            const uint2* kv0 = reinterpret_cast<const uint2*>(g_kv + (size_t)s0 * 256);
            const uint2* kv1 = reinterpret_cast<const uint2*>(g_kv + (size_t)s1 * 256);
            uint2 k0u = kv0[lane],      k1u = kv1[lane];
            uint2 v0u = kv0[32 + lane], v1u = kv1[32 + lane];

            float2 k0a = __half22float2(*reinterpret_cast<__half2*>(&k0u.x));
            float2 k0b = __half22float2(*reinterpret_cast<__half2*>(&k0u.y));
            float2 k1a = __half22float2(*reinterpret_cast<__half2*>(&k1u.x));
            float2 k1b = __half22float2(*reinterpret_cast<__half2*>(&k1u.y));

            float p0 = qv.x * k0a.x + qv.y * k0a.y + qv.z * k0b.x + qv.w * k0b.y;
            float p1 = qv.x * k1a.x + qv.y * k1a.y + qv.z * k1b.x + qv.w * k1b.y;
            p0 += __shfl_xor_sync(0xffffffffu, p0, 1);
            p1 += __shfl_xor_sync(0xffffffffu, p1, 1);
            p0 += __shfl_xor_sync(0xffffffffu, p0, 2);
            p1 += __shfl_xor_sync(0xffffffffu, p1, 2);
            float sc0 = p0 * 0.25f, sc1 = p1 * 0.25f;

            float2 v0a = __half22float2(*reinterpret_cast<__half2*>(&v0u.x));
            float2 v0b = __half22float2(*reinterpret_cast<__half2*>(&v0u.y));
            float2 v1a = __half22float2(*reinterpret_cast<__half2*>(&v1u.x));
            float2 v1b = __half22float2(*reinterpret_cast<__half2*>(&v1u.y));

            float mn0 = fmaxf(mA, sc0);
            float mn1 = fmaxf(mB, sc1);
            float c0 = __expf(mA - mn0), w0 = __expf(sc0 - mn0);
            float c1 = __expf(mB - mn1), w1 = __expf(sc1 - mn1);
            sA = sA * c0 + w0;
            sB = sB * c1 + w1;
            axA = axA * c0 + w0 * v0a.x;  axB = axB * c1 + w1 * v1a.x;
            ayA = ayA * c0 + w0 * v0a.y;  ayB = ayB * c1 + w1 * v1a.y;
            azA = azA * c0 + w0 * v0b.x;  azB = azB * c1 + w1 * v1b.x;
            awA = awA * c0 + w0 * v0b.y;  awB = awB * c1 + w1 * v1b.y;
            mA = mn0; mB = mn1;
        }
        if (j < nload) {
            int s0 = __shfl_sync(0xffffffffu, sj, j);
            const uint2* kv0 = reinterpret_cast<const uint2*>(g_kv + (size_t)s0 * 256);
            uint2 k0u = kv0[lane];
            uint2 v0u = kv0[32 + lane];
            float2 k0a = __half22float2(*reinterpret_cast<__half2*>(&k0u.x));
            float2 k0b = __half22float2(*reinterpret_cast<__half2*>(&k0u.y));
            float p0 = qv.x * k0a.x + qv.y * k0a.y + qv.z * k0b.x + qv.w * k0b.y;
            p0 += __shfl_xor_sync(0xffffffffu, p0, 1);
            p0 += __shfl_xor_sync(0xffffffffu, p0, 2);
            float sc0 = p0 * 0.25f;
            float2 v0a = __half22float2(*reinterpret_cast<__half2*>(&v0u.x));
            float2 v0b = __half22float2(*reinterpret_cast<__half2*>(&v0u.y));
            float mn0 = fmaxf(mA, sc0);
            float c0 = __expf(mA - mn0), w0 = __expf(sc0 - mn0);
            sA = sA * c0 + w0;
            axA = axA * c0 + w0 * v0a.x;
            ayA = ayA * c0 + w0 * v0a.y;
            azA = azA * c0 + w0 * v0b.x;
            awA = awA * c0 + w0 * v0b.y;
            mA = mn0;
        }
        t += nload;
    }

    float m = fmaxf(mA, mB);
    float cA = __expf(mA - m), cB = __expf(mB - m);
    float sum = sA * cA + sB * cB;
    float ax = axA * cA + axB * cB;
    float ay = ayA * cA + ayB * cB;
    float az = azA * cA + azB * cB;
    float aw = awA * cA + awB * cB;

    float inv = 1.f / (sum + 1e-9f);
    float4 o;
    o.x = fmaxf(ax * inv, 0.f);
    o.y = fmaxf(ay * inv, 0.f);
    o.z = fmaxf(az * inv, 0.f);
    o.w = fmaxf(aw * inv, 0.f);
    *reinterpret_cast<float4*>(zout + (size_t)node * ldz + lane * 4) = o;
    if (WXT) {
        __half2 h0 = __floats2half2_rn(o.x, o.y);
        __half2 h1 = __floats2half2_rn(o.z, o.w);
        *reinterpret_cast<__half2*>(g_xt + (size_t)node * H_DIM + lane * 4)     = h0;
        *reinterpret_cast<__half2*>(g_xt + (size_t)node * H_DIM + lane * 4 + 2) = h1;
    }
}

// ---------------- host ----------------------------------------------------------
extern "C" void kernel_launch(void* const* d_in, const int* in_sizes, int n_in,
                              void* d_out, int out_size)
{
    const float* obs = (const float*)d_in[0];
    const int*   src = (const int*)d_in[1];
    const int*   dst = (const int*)d_in[2];
    const float* W1  = (const float*)d_in[3];  const float* b1  = (const float*)d_in[4];
    const float* W2  = (const float*)d_in[5];  const float* b2  = (const float*)d_in[6];
    const float* Wq1 = (const float*)d_in[7];  const float* bq1 = (const float*)d_in[8];
    const float* Wk1 = (const float*)d_in[9];  const float* bk1 = (const float*)d_in[10];
    const float* Wv1 = (const float*)d_in[11]; const float* bv1 = (const float*)d_in[12];
    const float* Wq2 = (const float*)d_in[13]; const float* bq2 = (const float*)d_in[14];
    const float* Wk2 = (const float*)d_in[15]; const float* bk2 = (const float*)d_in[16];
    const float* Wv2 = (const float*)d_in[17]; const float* bv2 = (const float*)d_in[18];
    float* out = (float*)d_out;

    __half *p_obsT, *p_h1, *p_xt, *p_W1t, *p_W2t, *p_Wt1, *p_Wt2;
    float *p_bp1, *p_bp2;
    cudaGetSymbolAddress((void**)&p_obsT, g_obsT);
    cudaGetSymbolAddress((void**)&p_h1,   g_h1);
    cudaGetSymbolAddress((void**)&p_xt,   g_xt);
    cudaGetSymbolAddress((void**)&p_W1t,  g_W1t);
    cudaGetSymbolAddress((void**)&p_W2t,  g_W2t);
    cudaGetSymbolAddress((void**)&p_Wt1,  g_Wt1);
    cudaGetSymbolAddress((void**)&p_Wt2,  g_Wt2);
    cudaGetSymbolAddress((void**)&p_bp1,  g_bp1);
    cudaGetSymbolAddress((void**)&p_bp2,  g_bp2);

    cudaFuncSetAttribute(gemm_tc<0>, cudaFuncAttributeMaxDynamicSharedMemorySize, GEMM_SMEM);
    cudaFuncSetAttribute(gemm_tc<1>, cudaFuncAttributeMaxDynamicSharedMemorySize, GEMM_SMEM);
    cudaFuncSetAttribute(gemm_tc<2>, cudaFuncAttributeMaxDynamicSharedMemorySize, GEMM_SMEM);

    const int MT = (N_NODES + 127) / 128;   // 391

    // prep (obs cvt + weight packs + edge-degree count)
    k_prep<<<PREP_BLOCKS, 256>>>(obs, dst, W1, W2,
                                 Wq1, bq1, Wk1, bk1, Wv1, bv1,
                                 Wq2, bq2, Wk2, bk2, Wv2, bv2);

    // CSR (2 launches)
    k_scan_lb<<<NB_SCAN, 256>>>();
    k_scatter<<<(N_EDGES + 255) / 256, 256>>>(src, dst);

    // MLP encoder
    gemm_tc<0><<<dim3(MT, ENC_H / 128), 256, GEMM_SMEM>>>(
        p_obsT, OBS_DIM, p_W1t, b1, nullptr, 0, p_h1, ENC_H, N_NODES, OBS_DIM);
    gemm_tc<1><<<dim3(MT, 1), 256, GEMM_SMEM>>>(
        p_h1, ENC_H, p_W2t, b2, out + 0, OUT_LD, p_xt, H_DIM, N_NODES, ENC_H);

    // GAT layer 1
    gemm_tc<2><<<dim3(MT, 3), 256, GEMM_SMEM>>>(
        p_xt, H_DIM, p_Wt1, p_bp1, nullptr, 0, nullptr, 0, N_NODES, H_DIM);
    k_gat<true><<<(N_NODES * 32 + 255) / 256, 256>>>(out + H_DIM, OUT_LD);

    // GAT layer 2
    gemm_tc<2><<<dim3(MT, 3), 256, GEMM_SMEM>>>(
        p_xt, H_DIM, p_Wt2, p_bp2, nullptr, 0, nullptr, 0, N_NODES, H_DIM);
    k_gat<false><<<(N_NODES * 32 + 255) / 256, 256>>>(out + 2 * H_DIM, OUT_LD);
}

// round 9
// speedup vs baseline: 3.9611x; 1.0213x over previous
#include <cuda_runtime.h>
#include <cuda_fp16.h>
#include <cstdint>
#include <math.h>

#define N_NODES 50000
#define N_EDGES 800000
#define OBS_DIM 128
#define H_DIM   128
#define ENC_H   512
#define OUT_LD  384
#define NB_SCAN 196   // ceil(50000/256)

// ---------------- scratch ------------------------------------------------------
__device__ __half   g_obsT[(size_t)N_NODES * OBS_DIM];  // fp16 obs
__device__ __half   g_h1[(size_t)N_NODES * ENC_H];      // fp16 MLP hidden
__device__ __half   g_xt[(size_t)N_NODES * H_DIM];      // fp16 current x (GEMM A)
__device__ float    g_q [(size_t)N_NODES * H_DIM];      // fp32 q
__device__ __half   g_kv[(size_t)N_NODES * 256];        // fp16 k|v packed per node
__device__ __half   g_W1t[512 * 128];                   // fp16 [N,K] weights
__device__ __half   g_W2t[128 * 512];
__device__ __half   g_Wt1[384 * 128];
__device__ __half   g_Wt2[384 * 128];
__device__ float    g_bp1[384];
__device__ float    g_bp2[384];
__device__ int      g_deg[N_NODES];
__device__ int      g_off[N_NODES + 1];
__device__ int      g_pos[N_NODES];
__device__ int      g_srcs[N_EDGES];
__device__ unsigned long long g_lb[NB_SCAN];            // lookback state|value

#define LB_PARTIAL (1ull << 62)
#define LB_PREFIX  (2ull << 62)
#define LB_MASK    (3ull << 62)

// ---------------- helpers ------------------------------------------------------
__device__ __forceinline__ uint32_t smem_u32(const void* p) {
    uint32_t a;
    asm("{ .reg .u64 t; cvta.to.shared.u64 t, %1; cvt.u32.u64 %0, t; }" : "=r"(a) : "l"(p));
    return a;
}
__device__ __forceinline__ void cp16(uint32_t sm_addr, const void* g, int nbytes) {
    asm volatile("cp.async.cg.shared.global [%0], [%1], 16, %2;"
                 :: "r"(sm_addr), "l"(g), "r"(nbytes) : "memory");
}
__device__ __forceinline__ void cp_commit() {
    asm volatile("cp.async.commit_group;" ::: "memory");
}
template <int N>
__device__ __forceinline__ void cp_wait() {
    asm volatile("cp.async.wait_group %0;" :: "n"(N) : "memory");
}
__device__ __forceinline__ void mma_f16(float* c, const uint32_t* a, const uint32_t* b) {
    asm volatile(
        "mma.sync.aligned.m16n8k16.row.col.f32.f16.f16.f32 "
        "{%0,%1,%2,%3}, {%4,%5,%6,%7}, {%8,%9}, {%0,%1,%2,%3};\n"
        : "+f"(c[0]), "+f"(c[1]), "+f"(c[2]), "+f"(c[3])
        : "r"(a[0]), "r"(a[1]), "r"(a[2]), "r"(a[3]), "r"(b[0]), "r"(b[1]));
}
__device__ __forceinline__ void ldsm_x4(uint32_t& r0, uint32_t& r1, uint32_t& r2, uint32_t& r3,
                                        uint32_t addr) {
    asm volatile("ldmatrix.sync.aligned.m8n8.x4.shared.b16 {%0,%1,%2,%3}, [%4];"
                 : "=r"(r0), "=r"(r1), "=r"(r2), "=r"(r3) : "r"(addr));
}

// ---------------- pipelined FP16 GEMM (ldmatrix fragments) ----------------------
// C[M,N] = A[M,K] @ Bt^T (+bias); A half [M,K](lda), Bt half [Ntot,K].
// CTA tile 128x128, BK=32 halves, 3-stage cp.async, 80 B smem row stride.
// Modes: 0 = half out (+relu); 1 = fp32 out + half xt (+relu); 2 = qkv split.
#define SROW_B   80
#define ST_OP_B  (128 * SROW_B)         // 10240 B per operand per stage
#define ST_BYTES (2 * ST_OP_B)          // 20480
#define GEMM_SMEM (3 * ST_BYTES)        // 61440

__device__ __forceinline__ void load_stage(
    uint32_t sbase, int stage, const __half* __restrict__ A, int lda,
    const __half* __restrict__ Bt, int K, int rowBase, int colBase,
    int k0, int M, int tid)
{
    uint32_t st = sbase + stage * ST_BYTES;
    #pragma unroll
    for (int p = 0; p < 2; p++) {
        int idx = tid + (p << 8);            // 0..511
        int row = idx >> 2;                  // 0..127
        int kc  = idx & 3;                   // 0..3 (16B = 8 halves each)
        uint32_t off = row * SROW_B + kc * 16;
        int gr = rowBase + row;
        int okA = (gr < M) ? 16 : 0;
        const __half* ga = A + (size_t)(okA ? gr : 0) * lda + k0 + kc * 8;
        cp16(st + off, ga, okA);
        const __half* gb = Bt + (size_t)(colBase + row) * K + k0 + kc * 8;
        cp16(st + ST_OP_B + off, gb, 16);
    }
    cp_commit();
}

template <int MODE>
__global__ __launch_bounds__(256, 2)
void gemm_tc(const __half* __restrict__ A, int lda,
             const __half* __restrict__ Bt,
             const float* __restrict__ bias,
             float* __restrict__ C, int ldc,
             __half* __restrict__ Ct, int ldct,
             int M, int K)
{
    extern __shared__ char sm[];
    const uint32_t sbase = smem_u32(sm);
    const int tid  = threadIdx.x;
    const int lane = tid & 31;
    const int w    = tid >> 5;
    const int gid  = lane >> 2;
    const int tig  = lane & 3;
    const int warpM = w >> 2;
    const int warpN = w & 3;
    const int rowBase = blockIdx.x * 128;
    const int colBase = blockIdx.y * 128;
    const int nCh = K >> 5;

    // ldmatrix per-thread source rows (within the 128-row tile):
    const int sub = lane >> 3, lr = lane & 7;
    // A x4 (per mt): matrices = (m0-7,k0-7),(m8-15,k0-7),(m0-7,k8-15),(m8-15,k8-15)
    const uint32_t aOff = (uint32_t)(warpM * 64 + ((sub & 1) << 3) + lr) * SROW_B
                        + ((uint32_t)(sub >> 1) << 4);
    // B x4 (per nt-pair p): matrices = (nt0,k0-7),(nt0,k8-15),(nt1,k0-7),(nt1,k8-15)
    const uint32_t bOff = ST_OP_B
                        + (uint32_t)(warpN * 32 + ((sub >> 1) << 3) + lr) * SROW_B
                        + ((uint32_t)(sub & 1) << 4);

    float acc[4][4][4];
    #pragma unroll
    for (int mt = 0; mt < 4; mt++)
        #pragma unroll
        for (int nt = 0; nt < 4; nt++)
            #pragma unroll
            for (int j = 0; j < 4; j++) acc[mt][nt][j] = 0.f;

    load_stage(sbase, 0, A, lda, Bt, K, rowBase, colBase, 0, M, tid);
    load_stage(sbase, 1, A, lda, Bt, K, rowBase, colBase, 32, M, tid);

    int stage = 0;
    #pragma unroll 1
    for (int c = 0; c < nCh; c++) {
        if (c + 1 < nCh) cp_wait<1>(); else cp_wait<0>();
        __syncthreads();
        if (c + 2 < nCh) {
            int ns = stage + 2; if (ns >= 3) ns -= 3;
            load_stage(sbase, ns, A, lda, Bt, K, rowBase, colBase, (c + 2) << 5, M, tid);
        }
        const uint32_t stA = sbase + stage * ST_BYTES;
        #pragma unroll
        for (int kk = 0; kk < 2; kk++) {
            const uint32_t kb = (uint32_t)kk << 5;   // 32 B per k-halfstep
            uint32_t af[4][4], bf[4][2];
            #pragma unroll
            for (int mt = 0; mt < 4; mt++)
                ldsm_x4(af[mt][0], af[mt][1], af[mt][2], af[mt][3],
                        stA + aOff + (uint32_t)(mt * 16) * SROW_B + kb);
            #pragma unroll
            for (int p = 0; p < 2; p++)
                ldsm_x4(bf[2 * p][0], bf[2 * p][1], bf[2 * p + 1][0], bf[2 * p + 1][1],
                        stA + bOff + (uint32_t)(p * 16) * SROW_B + kb);
            #pragma unroll
            for (int mt = 0; mt < 4; mt++)
                #pragma unroll
                for (int nt = 0; nt < 4; nt++)
                    mma_f16(acc[mt][nt], af[mt], bf[nt]);
        }
        stage++; if (stage >= 3) stage = 0;
    }

    #pragma unroll
    for (int mt = 0; mt < 4; mt++) {
        int r0 = rowBase + warpM * 64 + mt * 16 + gid;
        #pragma unroll
        for (int nt = 0; nt < 4; nt++) {
            int cc = colBase + warpN * 32 + nt * 8 + tig * 2;
            float2 bi = *reinterpret_cast<const float2*>(bias + cc);
            #pragma unroll
            for (int h = 0; h < 2; h++) {
                int r = r0 + h * 8;
                if (r < M) {
                    float ox = acc[mt][nt][h * 2 + 0] + bi.x;
                    float oy = acc[mt][nt][h * 2 + 1] + bi.y;
                    if (MODE != 2) { ox = fmaxf(ox, 0.f); oy = fmaxf(oy, 0.f); }
                    if (MODE == 0) {
                        *reinterpret_cast<__half2*>(Ct + (size_t)r * ldct + cc) =
                            __floats2half2_rn(ox, oy);
                    } else if (MODE == 1) {
                        *reinterpret_cast<float2*>(C + (size_t)r * ldc + cc) = make_float2(ox, oy);
                        *reinterpret_cast<__half2*>(Ct + (size_t)r * ldct + cc) =
                            __floats2half2_rn(ox, oy);
                    } else {
                        if (colBase == 0) {
                            *reinterpret_cast<float2*>(g_q + (size_t)r * H_DIM + cc) =
                                make_float2(ox, oy);
                        } else {
                            *reinterpret_cast<__half2*>(g_kv + (size_t)r * 256 + (cc - 128)) =
                                __floats2half2_rn(ox, oy);
                        }
                    }
                }
            }
        }
    }
}

// ---------------- fused prep: obs cvt + weight packs + edge count ---------------
#define PREP_BLOCKS 10015

__global__ void k_prep(const float* __restrict__ obs, const int* __restrict__ dst,
                       const float* __restrict__ W1, const float* __restrict__ W2,
                       const float* __restrict__ Wq1, const float* __restrict__ bq1,
                       const float* __restrict__ Wk1, const float* __restrict__ bk1,
                       const float* __restrict__ Wv1, const float* __restrict__ bv1,
                       const float* __restrict__ Wq2, const float* __restrict__ bq2,
                       const float* __restrict__ Wk2, const float* __restrict__ bk2,
                       const float* __restrict__ Wv2, const float* __restrict__ bv2)
{
    int b = blockIdx.x, t = threadIdx.x;
    if (b < 6250) {
        int i = (b * 256 + t) * 4;
        if (i < N_NODES * OBS_DIM) {
            float4 v = *reinterpret_cast<const float4*>(obs + i);
            *reinterpret_cast<__half2*>(g_obsT + i)     = __floats2half2_rn(v.x, v.y);
            *reinterpret_cast<__half2*>(g_obsT + i + 2) = __floats2half2_rn(v.z, v.w);
        }
    } else if (b < 6506) {
        int i = (b - 6250) * 256 + t;       // W1: [128,512] -> g_W1t [512][128]
        int k = i >> 9, n = i & 511;
        g_W1t[n * 128 + k] = __float2half_rn(W1[i]);
    } else if (b < 6762) {
        int i = (b - 6506) * 256 + t;       // W2: [512,128] -> g_W2t [128][512]
        int k = i >> 7, n = i & 127;
        g_W2t[n * 512 + k] = __float2half_rn(W2[i]);
    } else if (b < 6826) {
        int i = (b - 6762) * 256 + t;       // qkv1
        int k = i >> 7, n = i & 127;
        g_Wt1[n * 128 + k]         = __float2half_rn(Wq1[i]);
        g_Wt1[(n + 128) * 128 + k] = __float2half_rn(Wk1[i]);
        g_Wt1[(n + 256) * 128 + k] = __float2half_rn(Wv1[i]);
        if (i < 128) { g_bp1[i] = bq1[i]; g_bp1[128 + i] = bk1[i]; g_bp1[256 + i] = bv1[i]; }
    } else if (b < 6890) {
        int i = (b - 6826) * 256 + t;       // qkv2
        int k = i >> 7, n = i & 127;
        g_Wt2[n * 128 + k]         = __float2half_rn(Wq2[i]);
        g_Wt2[(n + 128) * 128 + k] = __float2half_rn(Wk2[i]);
        g_Wt2[(n + 256) * 128 + k] = __float2half_rn(Wv2[i]);
        if (i < 128) { g_bp2[i] = bq2[i]; g_bp2[128 + i] = bk2[i]; g_bp2[256 + i] = bv2[i]; }
    } else {
        int e = (b - 6890) * 256 + t;       // edge degree count (g_deg pre-zeroed)
        if (e < N_EDGES) atomicAdd(&g_deg[dst[e]], 1);
    }
}

// ---------------- CSR: single-pass decoupled-lookback scan ----------------------
__device__ __forceinline__ int block_excl_scan(int v, int tid) {
    int lane = tid & 31, w = tid >> 5;
    int x = v;
    #pragma unroll
    for (int d = 1; d < 32; d <<= 1) {
        int t = __shfl_up_sync(0xffffffffu, x, d);
        if (lane >= d) x += t;
    }
    __shared__ int ws[8];
    if (lane == 31) ws[w] = x;
    __syncthreads();
    if (w == 0) {
        int y = (lane < 8) ? ws[lane] : 0;
        #pragma unroll
        for (int d = 1; d < 8; d <<= 1) {
            int t = __shfl_up_sync(0xffffffffu, y, d);
            if (lane >= d) y += t;
        }
        if (lane < 8) ws[lane] = y;
    }
    __syncthreads();
    return x - v + ((w > 0) ? ws[w - 1] : 0);
}

__global__ void k_scan_lb() {
    int b = blockIdx.x, tid = threadIdx.x;
    int i = b * 256 + tid;
    int v = (i < N_NODES) ? g_deg[i] : 0;
    if (i < N_NODES) g_deg[i] = 0;          // reset for next call (invariant)
    int excl = block_excl_scan(v, tid);
    __shared__ int s_prefix;

    if (tid == 255) {
        unsigned long long agg = (unsigned long long)(excl + v);
        if (b == 0) atomicExch(&g_lb[0], LB_PREFIX | agg);
        else        atomicExch(&g_lb[b], LB_PARTIAL | agg);
    }
    if (tid == 0) {
        if (b == 0) s_prefix = 0;
        else {
            long long running = 0;
            int p = b - 1;
            for (;;) {
                unsigned long long x = atomicAdd(&g_lb[p], 0ull);
                unsigned long long st = x & LB_MASK;
                if (st == LB_PREFIX)  { running += (long long)(x & ~LB_MASK); break; }
                if (st == LB_PARTIAL) { running += (long long)(x & ~LB_MASK); p--; }
            }
            s_prefix = (int)running;
        }
    }
    __syncthreads();
    int pre = s_prefix;
    if (b > 0 && tid == 255)
        atomicExch(&g_lb[b], LB_PREFIX | (unsigned long long)(pre + excl + v));
    if (i < N_NODES) {
        int o = pre + excl;
        g_off[i] = o;
        g_pos[i] = o;
    }
    if (b == NB_SCAN - 1 && tid == 255) g_off[N_NODES] = pre + excl + v;
}

__global__ void k_scatter(const int* __restrict__ src, const int* __restrict__ dst) {
    int e = blockIdx.x * blockDim.x + threadIdx.x;
    if (e < NB_SCAN) g_lb[e] = 0ull;        // reset lookback for next call
    if (e < N_EDGES) {
        int d = dst[e];
        int idx = atomicAdd(&g_pos[d], 1);
        g_srcs[idx] = src[e];
    }
}

// ---------------- GAT: one warp per dst node, fp16 k/v, dual-state softmax ------
template <bool WXT>
__global__ void k_gat(float* __restrict__ zout, int ldz)
{
    int node = (blockIdx.x * blockDim.x + threadIdx.x) >> 5;
    int lane = threadIdx.x & 31;
    if (node >= N_NODES) return;

    const float4 qv = *reinterpret_cast<const float4*>(g_q + (size_t)node * H_DIM + lane * 4);

    float mA = -1e30f, sA = 0.f, axA = 0.f, ayA = 0.f, azA = 0.f, awA = 0.f;
    float mB = -1e30f, sB = 0.f, axB = 0.f, ayB = 0.f, azB = 0.f, awB = 0.f;

    int t = g_off[node], end = g_off[node + 1];
    while (t < end) {
        int nload = min(32, end - t);
        int sj = (lane < nload) ? __ldg(&g_srcs[t + lane]) : 0;
        int j = 0;
        for (; j + 1 < nload; j += 2) {
            int s0 = __shfl_sync(0xffffffffu, sj, j);
            int s1 = __shfl_sync(0xffffffffu, sj, j + 1);
            const uint2* kv0 = reinterpret_cast<const uint2*>(g_kv + (size_t)s0 * 256);
            const uint2* kv1 = reinterpret_cast<const uint2*>(g_kv + (size_t)s1 * 256);
            uint2 k0u = kv0[lane],      k1u = kv1[lane];
            uint2 v0u = kv0[32 + lane], v1u = kv1[32 + lane];

            float2 k0a = __half22float2(*reinterpret_cast<__half2*>(&k0u.x));
            float2 k0b = __half22float2(*reinterpret_cast<__half2*>(&k0u.y));
            float2 k1a = __half22float2(*reinterpret_cast<__half2*>(&k1u.x));
            float2 k1b = __half22float2(*reinterpret_cast<__half2*>(&k1u.y));

            float p0 = qv.x * k0a.x + qv.y * k0a.y + qv.z * k0b.x + qv.w * k0b.y;
            float p1 = qv.x * k1a.x + qv.y * k1a.y + qv.z * k1b.x + qv.w * k1b.y;
            p0 += __shfl_xor_sync(0xffffffffu, p0, 1);
            p1 += __shfl_xor_sync(0xffffffffu, p1, 1);
            p0 += __shfl_xor_sync(0xffffffffu, p0, 2);
            p1 += __shfl_xor_sync(0xffffffffu, p1, 2);
            float sc0 = p0 * 0.25f, sc1 = p1 * 0.25f;

            float2 v0a = __half22float2(*reinterpret_cast<__half2*>(&v0u.x));
            float2 v0b = __half22float2(*reinterpret_cast<__half2*>(&v0u.y));
            float2 v1a = __half22float2(*reinterpret_cast<__half2*>(&v1u.x));
            float2 v1b = __half22float2(*reinterpret_cast<__half2*>(&v1u.y));

            float mn0 = fmaxf(mA, sc0);
            float mn1 = fmaxf(mB, sc1);
            float c0 = __expf(mA - mn0), w0 = __expf(sc0 - mn0);
            float c1 = __expf(mB - mn1), w1 = __expf(sc1 - mn1);
            sA = sA * c0 + w0;
            sB = sB * c1 + w1;
            axA = axA * c0 + w0 * v0a.x;  axB = axB * c1 + w1 * v1a.x;
            ayA = ayA * c0 + w0 * v0a.y;  ayB = ayB * c1 + w1 * v1a.y;
            azA = azA * c0 + w0 * v0b.x;  azB = azB * c1 + w1 * v1b.x;
            awA = awA * c0 + w0 * v0b.y;  awB = awB * c1 + w1 * v1b.y;
            mA = mn0; mB = mn1;
        }
        if (j < nload) {
            int s0 = __shfl_sync(0xffffffffu, sj, j);
            const uint2* kv0 = reinterpret_cast<const uint2*>(g_kv + (size_t)s0 * 256);
            uint2 k0u = kv0[lane];
            uint2 v0u = kv0[32 + lane];
            float2 k0a = __half22float2(*reinterpret_cast<__half2*>(&k0u.x));
            float2 k0b = __half22float2(*reinterpret_cast<__half2*>(&k0u.y));
            float p0 = qv.x * k0a.x + qv.y * k0a.y + qv.z * k0b.x + qv.w * k0b.y;
            p0 += __shfl_xor_sync(0xffffffffu, p0, 1);
            p0 += __shfl_xor_sync(0xffffffffu, p0, 2);
            float sc0 = p0 * 0.25f;
            float2 v0a = __half22float2(*reinterpret_cast<__half2*>(&v0u.x));
            float2 v0b = __half22float2(*reinterpret_cast<__half2*>(&v0u.y));
            float mn0 = fmaxf(mA, sc0);
            float c0 = __expf(mA - mn0), w0 = __expf(sc0 - mn0);
            sA = sA * c0 + w0;
            axA = axA * c0 + w0 * v0a.x;
            ayA = ayA * c0 + w0 * v0a.y;
            azA = azA * c0 + w0 * v0b.x;
            awA = awA * c0 + w0 * v0b.y;
            mA = mn0;
        }
        t += nload;
    }

    float m = fmaxf(mA, mB);
    float cA = __expf(mA - m), cB = __expf(mB - m);
    float sum = sA * cA + sB * cB;
    float ax = axA * cA + axB * cB;
    float ay = ayA * cA + ayB * cB;
    float az = azA * cA + azB * cB;
    float aw = awA * cA + awB * cB;

    float inv = 1.f / (sum + 1e-9f);
    float4 o;
    o.x = fmaxf(ax * inv, 0.f);
    o.y = fmaxf(ay * inv, 0.f);
    o.z = fmaxf(az * inv, 0.f);
    o.w = fmaxf(aw * inv, 0.f);
    *reinterpret_cast<float4*>(zout + (size_t)node * ldz + lane * 4) = o;
    if (WXT) {
        __half2 h0 = __floats2half2_rn(o.x, o.y);
        __half2 h1 = __floats2half2_rn(o.z, o.w);
        *reinterpret_cast<__half2*>(g_xt + (size_t)node * H_DIM + lane * 4)     = h0;
        *reinterpret_cast<__half2*>(g_xt + (size_t)node * H_DIM + lane * 4 + 2) = h1;
    }
}

// ---------------- host ----------------------------------------------------------
extern "C" void kernel_launch(void* const* d_in, const int* in_sizes, int n_in,
                              void* d_out, int out_size)
{
    const float* obs = (const float*)d_in[0];
    const int*   src = (const int*)d_in[1];
    const int*   dst = (const int*)d_in[2];
    const float* W1  = (const float*)d_in[3];  const float* b1  = (const float*)d_in[4];
    const float* W2  = (const float*)d_in[5];  const float* b2  = (const float*)d_in[6];
    const float* Wq1 = (const float*)d_in[7];  const float* bq1 = (const float*)d_in[8];
    const float* Wk1 = (const float*)d_in[9];  const float* bk1 = (const float*)d_in[10];
    const float* Wv1 = (const float*)d_in[11]; const float* bv1 = (const float*)d_in[12];
    const float* Wq2 = (const float*)d_in[13]; const float* bq2 = (const float*)d_in[14];
    const float* Wk2 = (const float*)d_in[15]; const float* bk2 = (const float*)d_in[16];
    const float* Wv2 = (const float*)d_in[17]; const float* bv2 = (const float*)d_in[18];
    float* out = (float*)d_out;

    __half *p_obsT, *p_h1, *p_xt, *p_W1t, *p_W2t, *p_Wt1, *p_Wt2;
    float *p_bp1, *p_bp2;
    cudaGetSymbolAddress((void**)&p_obsT, g_obsT);
    cudaGetSymbolAddress((void**)&p_h1,   g_h1);
    cudaGetSymbolAddress((void**)&p_xt,   g_xt);
    cudaGetSymbolAddress((void**)&p_W1t,  g_W1t);
    cudaGetSymbolAddress((void**)&p_W2t,  g_W2t);
    cudaGetSymbolAddress((void**)&p_Wt1,  g_Wt1);
    cudaGetSymbolAddress((void**)&p_Wt2,  g_Wt2);
    cudaGetSymbolAddress((void**)&p_bp1,  g_bp1);
    cudaGetSymbolAddress((void**)&p_bp2,  g_bp2);

    cudaFuncSetAttribute(gemm_tc<0>, cudaFuncAttributeMaxDynamicSharedMemorySize, GEMM_SMEM);
    cudaFuncSetAttribute(gemm_tc<1>, cudaFuncAttributeMaxDynamicSharedMemorySize, GEMM_SMEM);
    cudaFuncSetAttribute(gemm_tc<2>, cudaFuncAttributeMaxDynamicSharedMemorySize, GEMM_SMEM);

    const int MT = (N_NODES + 127) / 128;   // 391

    // prep (obs cvt + weight packs + edge-degree count)
    k_prep<<<PREP_BLOCKS, 256>>>(obs, dst, W1, W2,
                                 Wq1, bq1, Wk1, bk1, Wv1, bv1,
                                 Wq2, bq2, Wk2, bk2, Wv2, bv2);

    // CSR (2 launches)
    k_scan_lb<<<NB_SCAN, 256>>>();
    k_scatter<<<(N_EDGES + 255) / 256, 256>>>(src, dst);

    // MLP encoder
    gemm_tc<0><<<dim3(MT, ENC_H / 128), 256, GEMM_SMEM>>>(
        p_obsT, OBS_DIM, p_W1t, b1, nullptr, 0, p_h1, ENC_H, N_NODES, OBS_DIM);
    gemm_tc<1><<<dim3(MT, 1), 256, GEMM_SMEM>>>(
        p_h1, ENC_H, p_W2t, b2, out + 0, OUT_LD, p_xt, H_DIM, N_NODES, ENC_H);

    // GAT layer 1
    gemm_tc<2><<<dim3(MT, 3), 256, GEMM_SMEM>>>(
        p_xt, H_DIM, p_Wt1, p_bp1, nullptr, 0, nullptr, 0, N_NODES, H_DIM);
    k_gat<true><<<(N_NODES * 32 + 255) / 256, 256>>>(out + H_DIM, OUT_LD);

    // GAT layer 2
    gemm_tc<2><<<dim3(MT, 3), 256, GEMM_SMEM>>>(
        p_xt, H_DIM, p_Wt2, p_bp2, nullptr, 0, nullptr, 0, N_NODES, H_DIM);
    k_gat<false><<<(N_NODES * 32 + 255) / 256, 256>>>(out + 2 * H_DIM, OUT_LD);
}

// round 10
// speedup vs baseline: 4.0758x; 1.0290x over previous
#include <cuda_runtime.h>
#include <cuda_fp16.h>
#include <cstdint>
#include <math.h>

#define N_NODES 50000
#define N_EDGES 800000
#define OBS_DIM 128
#define H_DIM   128
#define ENC_H   512
#define OUT_LD  384
#define NB_SCAN 196   // ceil(50000/256)
#define NB_SCAT 3125  // ceil(800000/256)

// ---------------- scratch ------------------------------------------------------
__device__ __half   g_obsT[(size_t)N_NODES * OBS_DIM];  // fp16 obs
__device__ __half   g_h1[(size_t)N_NODES * ENC_H];      // fp16 MLP hidden
__device__ __half   g_xt[(size_t)N_NODES * H_DIM];      // fp16 current x (GEMM A)
__device__ float    g_q [(size_t)N_NODES * H_DIM];      // fp32 q
__device__ __half   g_kv[(size_t)N_NODES * 256];        // fp16 k|v packed per node
__device__ __half   g_W1t[512 * 128];                   // fp16 [N,K] weights
__device__ __half   g_W2t[128 * 512];
__device__ __half   g_Wt1[384 * 128];
__device__ __half   g_Wt2[384 * 128];
__device__ float    g_bp1[384];
__device__ float    g_bp2[384];
__device__ int      g_deg[N_NODES];
__device__ int      g_off[N_NODES + 1];
__device__ int      g_pos[N_NODES];
__device__ int      g_srcs[N_EDGES];
__device__ unsigned long long g_lb[NB_SCAN];            // lookback state|value

#define LB_PARTIAL (1ull << 62)
#define LB_PREFIX  (2ull << 62)
#define LB_MASK    (3ull << 62)

// ---------------- helpers ------------------------------------------------------
__device__ __forceinline__ uint32_t smem_u32(const void* p) {
    uint32_t a;
    asm("{ .reg .u64 t; cvta.to.shared.u64 t, %1; cvt.u32.u64 %0, t; }" : "=r"(a) : "l"(p));
    return a;
}
__device__ __forceinline__ void cp16(uint32_t sm_addr, const void* g, int nbytes) {
    asm volatile("cp.async.cg.shared.global [%0], [%1], 16, %2;"
                 :: "r"(sm_addr), "l"(g), "r"(nbytes) : "memory");
}
__device__ __forceinline__ void cp_commit() {
    asm volatile("cp.async.commit_group;" ::: "memory");
}
template <int N>
__device__ __forceinline__ void cp_wait() {
    asm volatile("cp.async.wait_group %0;" :: "n"(N) : "memory");
}
__device__ __forceinline__ void mma_f16(float* c, const uint32_t* a, const uint32_t* b) {
    asm volatile(
        "mma.sync.aligned.m16n8k16.row.col.f32.f16.f16.f32 "
        "{%0,%1,%2,%3}, {%4,%5,%6,%7}, {%8,%9}, {%0,%1,%2,%3};\n"
        : "+f"(c[0]), "+f"(c[1]), "+f"(c[2]), "+f"(c[3])
        : "r"(a[0]), "r"(a[1]), "r"(a[2]), "r"(a[3]), "r"(b[0]), "r"(b[1]));
}
__device__ __forceinline__ void ldsm_x4(uint32_t& r0, uint32_t& r1, uint32_t& r2, uint32_t& r3,
                                        uint32_t addr) {
    asm volatile("ldmatrix.sync.aligned.m8n8.x4.shared.b16 {%0,%1,%2,%3}, [%4];"
                 : "=r"(r0), "=r"(r1), "=r"(r2), "=r"(r3) : "r"(addr));
}

// ---------------- CSR device blocks ---------------------------------------------
__device__ __forceinline__ int block_excl_scan(int v, int tid) {
    int lane = tid & 31, w = tid >> 5;
    int x = v;
    #pragma unroll
    for (int d = 1; d < 32; d <<= 1) {
        int t = __shfl_up_sync(0xffffffffu, x, d);
        if (lane >= d) x += t;
    }
    __shared__ int ws[8];
    if (lane == 31) ws[w] = x;
    __syncthreads();
    if (w == 0) {
        int y = (lane < 8) ? ws[lane] : 0;
        #pragma unroll
        for (int d = 1; d < 8; d <<= 1) {
            int t = __shfl_up_sync(0xffffffffu, y, d);
            if (lane >= d) y += t;
        }
        if (lane < 8) ws[lane] = y;
    }
    __syncthreads();
    return x - v + ((w > 0) ? ws[w - 1] : 0);
}

// decoupled-lookback scan block b: g_deg -> g_off/g_pos (re-zeros g_deg)
__device__ __forceinline__ void scan_block_fn(int b) {
    int tid = threadIdx.x;
    int i = b * 256 + tid;
    int v = (i < N_NODES) ? g_deg[i] : 0;
    if (i < N_NODES) g_deg[i] = 0;
    int excl = block_excl_scan(v, tid);
    __shared__ int s_prefix;

    if (tid == 255) {
        unsigned long long agg = (unsigned long long)(excl + v);
        if (b == 0) atomicExch(&g_lb[0], LB_PREFIX | agg);
        else        atomicExch(&g_lb[b], LB_PARTIAL | agg);
    }
    if (tid == 0) {
        if (b == 0) s_prefix = 0;
        else {
            long long running = 0;
            int p = b - 1;
            for (;;) {
                unsigned long long x = atomicAdd(&g_lb[p], 0ull);
                unsigned long long st = x & LB_MASK;
                if (st == LB_PREFIX)  { running += (long long)(x & ~LB_MASK); break; }
                if (st == LB_PARTIAL) { running += (long long)(x & ~LB_MASK); p--; }
            }
            s_prefix = (int)running;
        }
    }
    __syncthreads();
    int pre = s_prefix;
    if (b > 0 && tid == 255)
        atomicExch(&g_lb[b], LB_PREFIX | (unsigned long long)(pre + excl + v));
    if (i < N_NODES) {
        int o = pre + excl;
        g_off[i] = o;
        g_pos[i] = o;
    }
    if (b == NB_SCAN - 1 && tid == 255) g_off[N_NODES] = pre + excl + v;
}

__device__ __forceinline__ void scatter_block_fn(int b, const int* __restrict__ src,
                                                 const int* __restrict__ dst) {
    int e = b * 256 + threadIdx.x;
    if (e < NB_SCAN) g_lb[e] = 0ull;        // reset lookback for next call
    if (e < N_EDGES) {
        int d = dst[e];
        int idx = atomicAdd(&g_pos[d], 1);
        g_srcs[idx] = src[e];
    }
}

// ---------------- single-stage K=128 FP16 GEMM (ldmatrix) -----------------------
// C[M,128cols] = A[M,128] @ Bt^T (+bias); full K tile in smem, ONE sync.
// 272 B row stride (conflict-free ldmatrix). Grid 1D: [nGemm gemm blocks | extra].
// Modes: 0 = half out (+relu); 2 = qkv split. EXTRA: 0 none, 1 scan, 2 scatter.
#define K128_SROW 272
#define K128_OP   (128 * K128_SROW)     // 34816 B per operand
#define K128_SMEM (2 * K128_OP)         // 69632 B

template <int MODE, int EXTRA>
__global__ __launch_bounds__(256, 2)
void gemm_k128(const __half* __restrict__ A, int lda,
               const __half* __restrict__ Bt,
               const float* __restrict__ bias,
               __half* __restrict__ Ct, int ldct,
               int M, int MT_, int nGemm,
               const int* __restrict__ src, const int* __restrict__ dst)
{
    if (EXTRA != 0 && (int)blockIdx.x >= nGemm) {
        if (EXTRA == 1) scan_block_fn(blockIdx.x - nGemm);
        else            scatter_block_fn(blockIdx.x - nGemm, src, dst);
        return;
    }
    extern __shared__ char sm[];
    const uint32_t sbase = smem_u32(sm);
    const int tid  = threadIdx.x;
    const int lane = tid & 31;
    const int w    = tid >> 5;
    const int gid  = lane >> 2;
    const int tig  = lane & 3;
    const int warpM = w >> 2;
    const int warpN = w & 3;
    const int rowBase = ((int)blockIdx.x % MT_) * 128;
    const int colBase = ((int)blockIdx.x / MT_) * 128;

    // load full 128x128 tiles (A and B), one burst
    #pragma unroll
    for (int p = 0; p < 8; p++) {
        int idx = tid + (p << 8);            // 0..2047
        int row = idx >> 4;                  // 0..127
        int ch  = idx & 15;                  // 16B chunk
        uint32_t off = row * K128_SROW + (ch << 4);
        int gr = rowBase + row;
        int okA = (gr < M) ? 16 : 0;
        cp16(sbase + off, A + (size_t)(okA ? gr : 0) * lda + ch * 8, okA);
        cp16(sbase + K128_OP + off, Bt + (size_t)(colBase + row) * 128 + ch * 8, 16);
    }
    cp_commit();

    const int sub = lane >> 3, lr = lane & 7;
    const uint32_t aOff = (uint32_t)(warpM * 64 + ((sub & 1) << 3) + lr) * K128_SROW
                        + ((uint32_t)(sub >> 1) << 4);
    const uint32_t bOff = K128_OP
                        + (uint32_t)(warpN * 32 + ((sub >> 1) << 3) + lr) * K128_SROW
                        + ((uint32_t)(sub & 1) << 4);

    float acc[4][4][4];
    #pragma unroll
    for (int mt = 0; mt < 4; mt++)
        #pragma unroll
        for (int nt = 0; nt < 4; nt++)
            #pragma unroll
            for (int j = 0; j < 4; j++) acc[mt][nt][j] = 0.f;

    cp_wait<0>();
    __syncthreads();

    #pragma unroll
    for (int kk = 0; kk < 8; kk++) {
        const uint32_t kb = (uint32_t)kk << 5;   // 32 B per k-step of 16
        uint32_t af[4][4], bf[4][2];
        #pragma unroll
        for (int mt = 0; mt < 4; mt++)
            ldsm_x4(af[mt][0], af[mt][1], af[mt][2], af[mt][3],
                    sbase + aOff + (uint32_t)(mt * 16) * K128_SROW + kb);
        #pragma unroll
        for (int p = 0; p < 2; p++)
            ldsm_x4(bf[2 * p][0], bf[2 * p][1], bf[2 * p + 1][0], bf[2 * p + 1][1],
                    sbase + bOff + (uint32_t)(p * 16) * K128_SROW + kb);
        #pragma unroll
        for (int mt = 0; mt < 4; mt++)
            #pragma unroll
            for (int nt = 0; nt < 4; nt++)
                mma_f16(acc[mt][nt], af[mt], bf[nt]);
    }

    #pragma unroll
    for (int mt = 0; mt < 4; mt++) {
        int r0 = rowBase + warpM * 64 + mt * 16 + gid;
        #pragma unroll
        for (int nt = 0; nt < 4; nt++) {
            int cc = colBase + warpN * 32 + nt * 8 + tig * 2;
            float2 bi = *reinterpret_cast<const float2*>(bias + cc);
            #pragma unroll
            for (int h = 0; h < 2; h++) {
                int r = r0 + h * 8;
                if (r < M) {
                    float ox = acc[mt][nt][h * 2 + 0] + bi.x;
                    float oy = acc[mt][nt][h * 2 + 1] + bi.y;
                    if (MODE == 0) {
                        ox = fmaxf(ox, 0.f); oy = fmaxf(oy, 0.f);
                        *reinterpret_cast<__half2*>(Ct + (size_t)r * ldct + cc) =
                            __floats2half2_rn(ox, oy);
                    } else {
                        if (colBase == 0) {
                            *reinterpret_cast<float2*>(g_q + (size_t)r * H_DIM + cc) =
                                make_float2(ox, oy);
                        } else {
                            *reinterpret_cast<__half2*>(g_kv + (size_t)r * 256 + (cc - 128)) =
                                __floats2half2_rn(ox, oy);
                        }
                    }
                }
            }
        }
    }
}

// ---------------- pipelined FP16 GEMM (K=512, MODE 1: fp32 out + half xt) -------
#define SROW_B   80
#define ST_OP_B  (128 * SROW_B)
#define ST_BYTES (2 * ST_OP_B)
#define GEMM_SMEM (3 * ST_BYTES)

__device__ __forceinline__ void load_stage(
    uint32_t sbase, int stage, const __half* __restrict__ A, int lda,
    const __half* __restrict__ Bt, int K, int rowBase, int colBase,
    int k0, int M, int tid)
{
    uint32_t st = sbase + stage * ST_BYTES;
    #pragma unroll
    for (int p = 0; p < 2; p++) {
        int idx = tid + (p << 8);
        int row = idx >> 2;
        int kc  = idx & 3;
        uint32_t off = row * SROW_B + kc * 16;
        int gr = rowBase + row;
        int okA = (gr < M) ? 16 : 0;
        cp16(st + off, A + (size_t)(okA ? gr : 0) * lda + k0 + kc * 8, okA);
        cp16(st + ST_OP_B + off, Bt + (size_t)(colBase + row) * K + k0 + kc * 8, 16);
    }
    cp_commit();
}

__global__ __launch_bounds__(256, 2)
void gemm_k512(const __half* __restrict__ A, int lda,
               const __half* __restrict__ Bt,
               const float* __restrict__ bias,
               float* __restrict__ C, int ldc,
               __half* __restrict__ Ct, int ldct,
               int M, int K)
{
    extern __shared__ char sm[];
    const uint32_t sbase = smem_u32(sm);
    const int tid  = threadIdx.x;
    const int lane = tid & 31;
    const int w    = tid >> 5;
    const int gid  = lane >> 2;
    const int tig  = lane & 3;
    const int warpM = w >> 2;
    const int warpN = w & 3;
    const int rowBase = blockIdx.x * 128;
    const int colBase = blockIdx.y * 128;
    const int nCh = K >> 5;

    const int sub = lane >> 3, lr = lane & 7;
    const uint32_t aOff = (uint32_t)(warpM * 64 + ((sub & 1) << 3) + lr) * SROW_B
                        + ((uint32_t)(sub >> 1) << 4);
    const uint32_t bOff = ST_OP_B
                        + (uint32_t)(warpN * 32 + ((sub >> 1) << 3) + lr) * SROW_B
                        + ((uint32_t)(sub & 1) << 4);

    float acc[4][4][4];
    #pragma unroll
    for (int mt = 0; mt < 4; mt++)
        #pragma unroll
        for (int nt = 0; nt < 4; nt++)
            #pragma unroll
            for (int j = 0; j < 4; j++) acc[mt][nt][j] = 0.f;

    load_stage(sbase, 0, A, lda, Bt, K, rowBase, colBase, 0, M, tid);
    load_stage(sbase, 1, A, lda, Bt, K, rowBase, colBase, 32, M, tid);

    int stage = 0;
    #pragma unroll 1
    for (int c = 0; c < nCh; c++) {
        if (c + 1 < nCh) cp_wait<1>(); else cp_wait<0>();
        __syncthreads();
        if (c + 2 < nCh) {
            int ns = stage + 2; if (ns >= 3) ns -= 3;
            load_stage(sbase, ns, A, lda, Bt, K, rowBase, colBase, (c + 2) << 5, M, tid);
        }
        const uint32_t stA = sbase + stage * ST_BYTES;
        #pragma unroll
        for (int kk = 0; kk < 2; kk++) {
            const uint32_t kb = (uint32_t)kk << 5;
            uint32_t af[4][4], bf[4][2];
            #pragma unroll
            for (int mt = 0; mt < 4; mt++)
                ldsm_x4(af[mt][0], af[mt][1], af[mt][2], af[mt][3],
                        stA + aOff + (uint32_t)(mt * 16) * SROW_B + kb);
            #pragma unroll
            for (int p = 0; p < 2; p++)
                ldsm_x4(bf[2 * p][0], bf[2 * p][1], bf[2 * p + 1][0], bf[2 * p + 1][1],
                        stA + bOff + (uint32_t)(p * 16) * SROW_B + kb);
            #pragma unroll
            for (int mt = 0; mt < 4; mt++)
                #pragma unroll
                for (int nt = 0; nt < 4; nt++)
                    mma_f16(acc[mt][nt], af[mt], bf[nt]);
        }
        stage++; if (stage >= 3) stage = 0;
    }

    #pragma unroll
    for (int mt = 0; mt < 4; mt++) {
        int r0 = rowBase + warpM * 64 + mt * 16 + gid;
        #pragma unroll
        for (int nt = 0; nt < 4; nt++) {
            int cc = colBase + warpN * 32 + nt * 8 + tig * 2;
            float2 bi = *reinterpret_cast<const float2*>(bias + cc);
            #pragma unroll
            for (int h = 0; h < 2; h++) {
                int r = r0 + h * 8;
                if (r < M) {
                    float ox = fmaxf(acc[mt][nt][h * 2 + 0] + bi.x, 0.f);
                    float oy = fmaxf(acc[mt][nt][h * 2 + 1] + bi.y, 0.f);
                    *reinterpret_cast<float2*>(C + (size_t)r * ldc + cc) = make_float2(ox, oy);
                    *reinterpret_cast<__half2*>(Ct + (size_t)r * ldct + cc) =
                        __floats2half2_rn(ox, oy);
                }
            }
        }
    }
}

// ---------------- fused prep: obs cvt + weight packs + edge count ---------------
#define PREP_BLOCKS 10015

__global__ void k_prep(const float* __restrict__ obs, const int* __restrict__ dst,
                       const float* __restrict__ W1, const float* __restrict__ W2,
                       const float* __restrict__ Wq1, const float* __restrict__ bq1,
                       const float* __restrict__ Wk1, const float* __restrict__ bk1,
                       const float* __restrict__ Wv1, const float* __restrict__ bv1,
                       const float* __restrict__ Wq2, const float* __restrict__ bq2,
                       const float* __restrict__ Wk2, const float* __restrict__ bk2,
                       const float* __restrict__ Wv2, const float* __restrict__ bv2)
{
    int b = blockIdx.x, t = threadIdx.x;
    if (b < 6250) {
        int i = (b * 256 + t) * 4;
        if (i < N_NODES * OBS_DIM) {
            float4 v = *reinterpret_cast<const float4*>(obs + i);
            *reinterpret_cast<__half2*>(g_obsT + i)     = __floats2half2_rn(v.x, v.y);
            *reinterpret_cast<__half2*>(g_obsT + i + 2) = __floats2half2_rn(v.z, v.w);
        }
    } else if (b < 6506) {
        int i = (b - 6250) * 256 + t;       // W1: [128,512] -> g_W1t [512][128]
        int k = i >> 9, n = i & 511;
        g_W1t[n * 128 + k] = __float2half_rn(W1[i]);
    } else if (b < 6762) {
        int i = (b - 6506) * 256 + t;       // W2: [512,128] -> g_W2t [128][512]
        int k = i >> 7, n = i & 127;
        g_W2t[n * 512 + k] = __float2half_rn(W2[i]);
    } else if (b < 6826) {
        int i = (b - 6762) * 256 + t;       // qkv1
        int k = i >> 7, n = i & 127;
        g_Wt1[n * 128 + k]         = __float2half_rn(Wq1[i]);
        g_Wt1[(n + 128) * 128 + k] = __float2half_rn(Wk1[i]);
        g_Wt1[(n + 256) * 128 + k] = __float2half_rn(Wv1[i]);
        if (i < 128) { g_bp1[i] = bq1[i]; g_bp1[128 + i] = bk1[i]; g_bp1[256 + i] = bv1[i]; }
    } else if (b < 6890) {
        int i = (b - 6826) * 256 + t;       // qkv2
        int k = i >> 7, n = i & 127;
        g_Wt2[n * 128 + k]         = __float2half_rn(Wq2[i]);
        g_Wt2[(n + 128) * 128 + k] = __float2half_rn(Wk2[i]);
        g_Wt2[(n + 256) * 128 + k] = __float2half_rn(Wv2[i]);
        if (i < 128) { g_bp2[i] = bq2[i]; g_bp2[128 + i] = bk2[i]; g_bp2[256 + i] = bv2[i]; }
    } else {
        int e = (b - 6890) * 256 + t;       // edge degree count (g_deg pre-zeroed)
        if (e < N_EDGES) atomicAdd(&g_deg[dst[e]], 1);
    }
}

// ---------------- GAT: one warp per dst node, fp16 k/v, dual-state softmax ------
template <bool WXT>
__global__ void k_gat(float* __restrict__ zout, int ldz)
{
    int node = (blockIdx.x * blockDim.x + threadIdx.x) >> 5;
    int lane = threadIdx.x & 31;
    if (node >= N_NODES) return;

    const float4 qv = *reinterpret_cast<const float4*>(g_q + (size_t)node * H_DIM + lane * 4);

    float mA = -1e30f, sA = 0.f, axA = 0.f, ayA = 0.f, azA = 0.f, awA = 0.f;
    float mB = -1e30f, sB = 0.f, axB = 0.f, ayB = 0.f, azB = 0.f, awB = 0.f;

    int t = g_off[node], end = g_off[node + 1];
    while (t < end) {
        int nload = min(32, end - t);
        int sj = (lane < nload) ? __ldg(&g_srcs[t + lane]) : 0;
        int j = 0;
        for (; j + 1 < nload; j += 2) {
            int s0 = __shfl_sync(0xffffffffu, sj, j);
            int s1 = __shfl_sync(0xffffffffu, sj, j + 1);
            const uint2* kv0 = reinterpret_cast<const uint2*>(g_kv + (size_t)s0 * 256);
            const uint2* kv1 = reinterpret_cast<const uint2*>(g_kv + (size_t)s1 * 256);
            uint2 k0u = kv0[lane],      k1u = kv1[lane];
            uint2 v0u = kv0[32 + lane], v1u = kv1[32 + lane];

            float2 k0a = __half22float2(*reinterpret_cast<__half2*>(&k0u.x));
            float2 k0b = __half22float2(*reinterpret_cast<__half2*>(&k0u.y));
            float2 k1a = __half22float2(*reinterpret_cast<__half2*>(&k1u.x));
            float2 k1b = __half22float2(*reinterpret_cast<__half2*>(&k1u.y));

            float p0 = qv.x * k0a.x + qv.y * k0a.y + qv.z * k0b.x + qv.w * k0b.y;
            float p1 = qv.x * k1a.x + qv.y * k1a.y + qv.z * k1b.x + qv.w * k1b.y;
            p0 += __shfl_xor_sync(0xffffffffu, p0, 1);
            p1 += __shfl_xor_sync(0xffffffffu, p1, 1);
            p0 += __shfl_xor_sync(0xffffffffu, p0, 2);
            p1 += __shfl_xor_sync(0xffffffffu, p1, 2);
            float sc0 = p0 * 0.25f, sc1 = p1 * 0.25f;

            float2 v0a = __half22float2(*reinterpret_cast<__half2*>(&v0u.x));
            float2 v0b = __half22float2(*reinterpret_cast<__half2*>(&v0u.y));
            float2 v1a = __half22float2(*reinterpret_cast<__half2*>(&v1u.x));
            float2 v1b = __half22float2(*reinterpret_cast<__half2*>(&v1u.y));

            float mn0 = fmaxf(mA, sc0);
            float mn1 = fmaxf(mB, sc1);
            float c0 = __expf(mA - mn0), w0 = __expf(sc0 - mn0);
            float c1 = __expf(mB - mn1), w1 = __expf(sc1 - mn1);
            sA = sA * c0 + w0;
            sB = sB * c1 + w1;
            axA = axA * c0 + w0 * v0a.x;  axB = axB * c1 + w1 * v1a.x;
            ayA = ayA * c0 + w0 * v0a.y;  ayB = ayB * c1 + w1 * v1a.y;
            azA = azA * c0 + w0 * v0b.x;  azB = azB * c1 + w1 * v1b.x;
            awA = awA * c0 + w0 * v0b.y;  awB = awB * c1 + w1 * v1b.y;
            mA = mn0; mB = mn1;
        }
        if (j < nload) {
            int s0 = __shfl_sync(0xffffffffu, sj, j);
            const uint2* kv0 = reinterpret_cast<const uint2*>(g_kv + (size_t)s0 * 256);
            uint2 k0u = kv0[lane];
            uint2 v0u = kv0[32 + lane];
            float2 k0a = __half22float2(*reinterpret_cast<__half2*>(&k0u.x));
            float2 k0b = __half22float2(*reinterpret_cast<__half2*>(&k0u.y));
            float p0 = qv.x * k0a.x + qv.y * k0a.y + qv.z * k0b.x + qv.w * k0b.y;
            p0 += __shfl_xor_sync(0xffffffffu, p0, 1);
            p0 += __shfl_xor_sync(0xffffffffu, p0, 2);
            float sc0 = p0 * 0.25f;
            float2 v0a = __half22float2(*reinterpret_cast<__half2*>(&v0u.x));
            float2 v0b = __half22float2(*reinterpret_cast<__half2*>(&v0u.y));
            float mn0 = fmaxf(mA, sc0);
            float c0 = __expf(mA - mn0), w0 = __expf(sc0 - mn0);
            sA = sA * c0 + w0;
            axA = axA * c0 + w0 * v0a.x;
            ayA = ayA * c0 + w0 * v0a.y;
            azA = azA * c0 + w0 * v0b.x;
            awA = awA * c0 + w0 * v0b.y;
            mA = mn0;
        }
        t += nload;
    }

    float m = fmaxf(mA, mB);
    float cA = __expf(mA - m), cB = __expf(mB - m);
    float sum = sA * cA + sB * cB;
    float ax = axA * cA + axB * cB;
    float ay = ayA * cA + ayB * cB;
    float az = azA * cA + azB * cB;
    float aw = awA * cA + awB * cB;

    float inv = 1.f / (sum + 1e-9f);
    float4 o;
    o.x = fmaxf(ax * inv, 0.f);
    o.y = fmaxf(ay * inv, 0.f);
    o.z = fmaxf(az * inv, 0.f);
    o.w = fmaxf(aw * inv, 0.f);
    *reinterpret_cast<float4*>(zout + (size_t)node * ldz + lane * 4) = o;
    if (WXT) {
        __half2 h0 = __floats2half2_rn(o.x, o.y);
        __half2 h1 = __floats2half2_rn(o.z, o.w);
        *reinterpret_cast<__half2*>(g_xt + (size_t)node * H_DIM + lane * 4)     = h0;
        *reinterpret_cast<__half2*>(g_xt + (size_t)node * H_DIM + lane * 4 + 2) = h1;
    }
}

// ---------------- host ----------------------------------------------------------
extern "C" void kernel_launch(void* const* d_in, const int* in_sizes, int n_in,
                              void* d_out, int out_size)
{
    const float* obs = (const float*)d_in[0];
    const int*   src = (const int*)d_in[1];
    const int*   dst = (const int*)d_in[2];
    const float* W1  = (const float*)d_in[3];  const float* b1  = (const float*)d_in[4];
    const float* W2  = (const float*)d_in[5];  const float* b2  = (const float*)d_in[6];
    const float* Wq1 = (const float*)d_in[7];  const float* bq1 = (const float*)d_in[8];
    const float* Wk1 = (const float*)d_in[9];  const float* bk1 = (const float*)d_in[10];
    const float* Wv1 = (const float*)d_in[11]; const float* bv1 = (const float*)d_in[12];
    const float* Wq2 = (const float*)d_in[13]; const float* bq2 = (const float*)d_in[14];
    const float* Wk2 = (const float*)d_in[15]; const float* bk2 = (const float*)d_in[16];
    const float* Wv2 = (const float*)d_in[17]; const float* bv2 = (const float*)d_in[18];
    float* out = (float*)d_out;

    __half *p_obsT, *p_h1, *p_xt, *p_W1t, *p_W2t, *p_Wt1, *p_Wt2;
    float *p_bp1, *p_bp2;
    cudaGetSymbolAddress((void**)&p_obsT, g_obsT);
    cudaGetSymbolAddress((void**)&p_h1,   g_h1);
    cudaGetSymbolAddress((void**)&p_xt,   g_xt);
    cudaGetSymbolAddress((void**)&p_W1t,  g_W1t);
    cudaGetSymbolAddress((void**)&p_W2t,  g_W2t);
    cudaGetSymbolAddress((void**)&p_Wt1,  g_Wt1);
    cudaGetSymbolAddress((void**)&p_Wt2,  g_Wt2);
    cudaGetSymbolAddress((void**)&p_bp1,  g_bp1);
    cudaGetSymbolAddress((void**)&p_bp2,  g_bp2);

    cudaFuncSetAttribute(gemm_k128<0, 1>, cudaFuncAttributeMaxDynamicSharedMemorySize, K128_SMEM);
    cudaFuncSetAttribute(gemm_k128<2, 2>, cudaFuncAttributeMaxDynamicSharedMemorySize, K128_SMEM);
    cudaFuncSetAttribute(gemm_k128<2, 0>, cudaFuncAttributeMaxDynamicSharedMemorySize, K128_SMEM);
    cudaFuncSetAttribute(gemm_k512,       cudaFuncAttributeMaxDynamicSharedMemorySize, GEMM_SMEM);

    const int MT = (N_NODES + 127) / 128;   // 391

    // prep (obs cvt + weight packs + edge-degree count)
    k_prep<<<PREP_BLOCKS, 256>>>(obs, dst, W1, W2,
                                 Wq1, bq1, Wk1, bk1, Wv1, bv1,
                                 Wq2, bq2, Wk2, bk2, Wv2, bv2);

    // MLP layer 1 (K=128) + CSR scan folded in as trailing blocks
    gemm_k128<0, 1><<<MT * 4 + NB_SCAN, 256, K128_SMEM>>>(
        p_obsT, OBS_DIM, p_W1t, b1, p_h1, ENC_H, N_NODES, MT, MT * 4, nullptr, nullptr);

    // MLP layer 2 (K=512, pipelined): fp32 z1 -> out[:,0:128], fp16 xt
    gemm_k512<<<dim3(MT, 1), 256, GEMM_SMEM>>>(
        p_h1, ENC_H, p_W2t, b2, out + 0, OUT_LD, p_xt, H_DIM, N_NODES, ENC_H);

    // QKV layer 1 (K=128) + CSR scatter folded in as trailing blocks
    gemm_k128<2, 2><<<MT * 3 + NB_SCAT, 256, K128_SMEM>>>(
        p_xt, H_DIM, p_Wt1, p_bp1, nullptr, 0, N_NODES, MT, MT * 3, src, dst);
    k_gat<true><<<(N_NODES * 32 + 255) / 256, 256>>>(out + H_DIM, OUT_LD);

    // QKV layer 2 (K=128)
    gemm_k128<2, 0><<<MT * 3, 256, K128_SMEM>>>(
        p_xt, H_DIM, p_Wt2, p_bp2, nullptr, 0, N_NODES, MT, MT * 3, nullptr, nullptr);
    k_gat<false><<<(N_NODES * 32 + 255) / 256, 256>>>(out + 2 * H_DIM, OUT_LD);
}